// round 10
// baseline (speedup 1.0000x reference)
#include <cuda_runtime.h>
#include <cuda_bf16.h>
#include <cuda_fp16.h>
#include <math.h>
#include <stdint.h>

#define NN 50000
#define EE 800000
#define GG 512
#define HH 256
#define TT 32
#define LL 4

// ---------------- scratch (device globals) -----------------------------------
__device__ float g_bufA[NN * HH];           // residual h_{l-1}
__device__ __half g_hwh[NN * HH];           // fp16 GEMM output (gather source)
__device__ float g_bufC[NN * HH];           // agg output
__device__ float g_bufD[NN * HH];           // new h
__device__ int   g_cnt[NN];
__device__ int   g_cnt2[NN];
__device__ int   g_rowptr[NN + 1];
__device__ int   g_csr[EE];
__device__ float g_csrw[EE];
__device__ int   g_gcnt[GG];
__device__ int   g_goff[GG + 1];
__device__ float g_dinv[NN];
__device__ float g_P[100 * HH];
__device__ float g_Q[3 * HH];
__device__ float g_sums[LL * 2 * HH];
__device__ float g_pooled[GG * HH];
__device__ unsigned char g_Wimg[LL * 4 * 2 * 32768];

// ---------------- helpers ----------------------------------------------------
__device__ __forceinline__ uint32_t smem_u32(const void* p) {
    uint32_t a;
    asm("{ .reg .u64 t; cvta.to.shared.u64 t, %1; cvt.u32.u64 %0, t; }" : "=r"(a) : "l"(p));
    return a;
}
__device__ __forceinline__ uint32_t swz128(uint32_t o) { return o ^ ((o >> 3) & 0x70); }

__device__ __forceinline__ void ldsm4(uint32_t* r, uint32_t addr) {
    asm volatile("ldmatrix.sync.aligned.m8n8.x4.shared.b16 {%0,%1,%2,%3}, [%4];"
        : "=r"(r[0]), "=r"(r[1]), "=r"(r[2]), "=r"(r[3]) : "r"(addr));
}
__device__ __forceinline__ void mma16816(float* d, const uint32_t* a, const uint32_t* b) {
    asm volatile("mma.sync.aligned.m16n8k16.row.col.f32.bf16.bf16.f32 "
        "{%0,%1,%2,%3}, {%4,%5,%6,%7}, {%8,%9}, {%0,%1,%2,%3};"
        : "+f"(d[0]), "+f"(d[1]), "+f"(d[2]), "+f"(d[3])
        : "r"(a[0]), "r"(a[1]), "r"(a[2]), "r"(a[3]), "r"(b[0]), "r"(b[1]));
}
// pack lo-pair into bf16x2 with round-to-nearest
__device__ __forceinline__ uint32_t cvt_bf16x2(float lo, float hi) {
    uint32_t r;
    asm("cvt.rn.bf16x2.f32 %0, %1, %2;" : "=r"(r) : "f"(hi), "f"(lo));
    return r;
}
#define BAR_SYNC(id, cnt) asm volatile("bar.sync %0, %1;" :: "r"(id), "r"(cnt) : "memory")

// ---------------- setup ------------------------------------------------------
__global__ void k_zero_init(int* cnt, int* cnt2, int* gcnt, float* sums) {
    int i = blockIdx.x * blockDim.x + threadIdx.x;
    if (i < NN) { cnt[i] = 0; cnt2[i] = 0; }
    if (i < GG) gcnt[i] = 0;
    if (i < LL * 2 * HH) sums[i] = 0.f;
}

__global__ void k_count(const int* __restrict__ dst, const int* __restrict__ batch,
                        int* cnt, int* gcnt) {
    int e = blockIdx.x * blockDim.x + threadIdx.x;
    if (e < EE) atomicAdd(&cnt[dst[e]], 1);
    if (e < NN) atomicAdd(&gcnt[batch[e]], 1);
}

// ---------------- weights prep ----------------------------------------------
__global__ void k_weights(const float* __restrict__ gcn_W, unsigned char* __restrict__ img,
                          const float* __restrict__ atom_emb, const float* __restrict__ tag_emb,
                          const float* __restrict__ Wp, const float* __restrict__ bp,
                          float* P, float* Q) {
    int bid = blockIdx.x;
    int tid = threadIdx.x;
    if (bid < 1024) {
        int idx = bid * 256 + tid;
        int l = idx >> 16;
        int k = (idx >> 8) & 255;
        int n = idx & 255;
        float w = gcn_W[idx];
        __nv_bfloat16 hi = __float2bfloat16(w);
        __nv_bfloat16 lo = __float2bfloat16(w - __bfloat162float(hi));
        int kc = k >> 6, kk = k & 63;
        uint32_t off = swz128((uint32_t)(n * 128 + kk * 2));
        size_t base = ((size_t)(l * 4 + kc) * 2) * 32768;
        *(__nv_bfloat16*)(img + base + off) = hi;
        *(__nv_bfloat16*)(img + base + 32768 + off) = lo;
    } else {
        int r = bid - 1024;
        int c = tid;
        if (r < 100) {
            float acc = 0.f;
            #pragma unroll 8
            for (int k = 0; k < HH; k++) acc += atom_emb[r * HH + k] * Wp[k * HH + c];
            P[r * HH + c] = acc;
        } else {
            int t = r - 100;
            if (t < 3) {
                float acc = bp[c];
                #pragma unroll
                for (int k = 0; k < TT; k++) acc += tag_emb[t * TT + k] * Wp[(HH + k) * HH + c];
                Q[t * HH + c] = acc;
            }
        }
    }
}

__global__ __launch_bounds__(1024) void k_scan(const int* __restrict__ cnt, int* rowptr,
                                               float* dinv, const int* __restrict__ gcnt,
                                               int* goff) {
    __shared__ int wsum[32];
    const int tid = threadIdx.x;
    const int lane = tid & 31;
    const int w = tid >> 5;
    const int CH = (NN + 1023) / 1024;
    const int beg = tid * CH;
    const int end = min(beg + CH, NN);

    int tot = 0;
    for (int i = beg; i < end; i++) tot += cnt[i];
    int x = tot;
    #pragma unroll
    for (int o = 1; o < 32; o <<= 1) {
        int t = __shfl_up_sync(0xFFFFFFFFu, x, o);
        if (lane >= o) x += t;
    }
    if (lane == 31) wsum[w] = x;
    __syncthreads();
    if (w == 0) {
        int y = wsum[lane];
        #pragma unroll
        for (int o = 1; o < 32; o <<= 1) {
            int t = __shfl_up_sync(0xFFFFFFFFu, y, o);
            if (lane >= o) y += t;
        }
        wsum[lane] = y;
    }
    __syncthreads();
    int run = ((w > 0) ? wsum[w - 1] : 0) + x - tot;
    if (tid == 0) rowptr[0] = 0;
    for (int i = beg; i < end; i++) {
        int cv = cnt[i];
        dinv[i] = rsqrtf((float)cv + 1.0f);
        run += cv;
        rowptr[i + 1] = run;
    }
    __syncthreads();
    int vv = (tid < GG) ? gcnt[tid] : 0;
    int xg = vv;
    #pragma unroll
    for (int o = 1; o < 32; o <<= 1) {
        int t = __shfl_up_sync(0xFFFFFFFFu, xg, o);
        if (lane >= o) xg += t;
    }
    if (lane == 31) wsum[w] = xg;
    __syncthreads();
    if (w == 0) {
        int y = wsum[lane];
        #pragma unroll
        for (int o = 1; o < 32; o <<= 1) {
            int t = __shfl_up_sync(0xFFFFFFFFu, y, o);
            if (lane >= o) y += t;
        }
        wsum[lane] = y;
    }
    __syncthreads();
    int incl = ((w > 0) ? wsum[w - 1] : 0) + xg;
    if (tid == 0) goff[0] = 0;
    if (tid < GG) goff[tid + 1] = incl;
}

__global__ void k_fill_csr(const int* __restrict__ src, const int* __restrict__ dst,
                           const int* __restrict__ rowptr, const float* __restrict__ dinv,
                           int* cnt2, int* csr, float* csrw) {
    int e = blockIdx.x * blockDim.x + threadIdx.x;
    if (e < EE) {
        int s = src[e], d = dst[e];
        int pos = rowptr[d] + atomicAdd(&cnt2[d], 1);
        csr[pos] = s;
        csrw[pos] = dinv[s] * dinv[d];
    }
}

// ---------------- HMMA split-bf16 GEMM with fused prologue -------------------
#define SM_AH 0
#define SM_AL 16384
#define SM_BH 32768
#define SM_BL 49152
#define SM_GEMM 65536

__global__ __launch_bounds__(256, 2) void k_gemm_mma(
    const float* __restrict__ aggA, const float* __restrict__ hres,
    const float* __restrict__ sums, const float* __restrict__ bn_g,
    const float* __restrict__ bn_b,
    const unsigned char* __restrict__ WimgL,
    __half* __restrict__ C, int M,
    const float* __restrict__ P, const float* __restrict__ Q,
    const int* __restrict__ x, const int* __restrict__ tags,
    int mode, float* __restrict__ Aout) {
    extern __shared__ char smem[];
    const int tid = threadIdx.x;
    const int wid = tid >> 5;
    const int lane = tid & 31;
    const int wm = wid & 3;
    const int wn = wid >> 2;
    const uint32_t sb = smem_u32(smem);
    const int bm = blockIdx.y * 128;
    const int bn = blockIdx.x * 128;
    const int c4 = (tid & 15) << 2;
    const bool do_write_a = (blockIdx.x == 0);

    float acc[2][8][4];
    #pragma unroll
    for (int mi = 0; mi < 2; mi++)
        #pragma unroll
        for (int j = 0; j < 8; j++)
            #pragma unroll
            for (int q = 0; q < 4; q++) acc[mi][j][q] = 0.f;

    const float inv_n = 1.0f / (float)NN;

    for (int kc = 0; kc < 4; kc++) {
        const int col = kc * 64 + c4;
        float mu0 = 0.f, mu1 = 0.f, mu2 = 0.f, mu3 = 0.f;
        float rg0 = 0.f, rg1 = 0.f, rg2 = 0.f, rg3 = 0.f;
        float bb0 = 0.f, bb1 = 0.f, bb2 = 0.f, bb3 = 0.f;
        if (mode == 2) {
            mu0 = sums[col + 0] * inv_n;
            mu1 = sums[col + 1] * inv_n;
            mu2 = sums[col + 2] * inv_n;
            mu3 = sums[col + 3] * inv_n;
            float v0 = sums[HH + col + 0] * inv_n - mu0 * mu0;
            float v1 = sums[HH + col + 1] * inv_n - mu1 * mu1;
            float v2 = sums[HH + col + 2] * inv_n - mu2 * mu2;
            float v3 = sums[HH + col + 3] * inv_n - mu3 * mu3;
            rg0 = rsqrtf(v0 + 1e-5f) * bn_g[col + 0];
            rg1 = rsqrtf(v1 + 1e-5f) * bn_g[col + 1];
            rg2 = rsqrtf(v2 + 1e-5f) * bn_g[col + 2];
            rg3 = rsqrtf(v3 + 1e-5f) * bn_g[col + 3];
            bb0 = bn_b[col + 0];
            bb1 = bn_b[col + 1];
            bb2 = bn_b[col + 2];
            bb3 = bn_b[col + 3];
        }
        #pragma unroll
        for (int i = 0; i < 8; i++) {
            int r = (tid >> 4) + i * 16;
            int gr = bm + r;
            float4 v = make_float4(0.f, 0.f, 0.f, 0.f);
            if (gr < M) {
                if (mode == 1) {
                    int xi = x[gr], tg = tags[gr];
                    float4 p = *(const float4*)(P + (size_t)xi * HH + col);
                    float4 q = *(const float4*)(Q + (size_t)tg * HH + col);
                    v = make_float4(p.x + q.x, p.y + q.y, p.z + q.z, p.w + q.w);
                } else {
                    float4 a = *(const float4*)(aggA + (size_t)gr * HH + col);
                    float4 rr = *(const float4*)(hres + (size_t)gr * HH + col);
                    v.x = fmaxf((a.x - mu0) * rg0 + bb0, 0.f) + rr.x;
                    v.y = fmaxf((a.y - mu1) * rg1 + bb1, 0.f) + rr.y;
                    v.z = fmaxf((a.z - mu2) * rg2 + bb2, 0.f) + rr.z;
                    v.w = fmaxf((a.w - mu3) * rg3 + bb3, 0.f) + rr.w;
                }
                if (do_write_a) *(float4*)(Aout + (size_t)gr * HH + col) = v;
            }
            // truncation split: hi = top 16 bits (PRMT); lo = v - hi (bf16 rn)
            uint32_t ax = __float_as_uint(v.x), ay = __float_as_uint(v.y);
            uint32_t az = __float_as_uint(v.z), aw = __float_as_uint(v.w);
            uint2 hv = make_uint2(__byte_perm(ax, ay, 0x7632),
                                  __byte_perm(az, aw, 0x7632));
            float lx = v.x - __uint_as_float(ax & 0xFFFF0000u);
            float ly = v.y - __uint_as_float(ay & 0xFFFF0000u);
            float lz = v.z - __uint_as_float(az & 0xFFFF0000u);
            float lw = v.w - __uint_as_float(aw & 0xFFFF0000u);
            uint2 lv = make_uint2(cvt_bf16x2(lx, ly), cvt_bf16x2(lz, lw));
            uint32_t off = swz128((uint32_t)(r * 128 + c4 * 2));
            *(uint2*)(smem + SM_AH + off) = hv;
            *(uint2*)(smem + SM_AL + off) = lv;
        }
        {
            const uint4* srcH = (const uint4*)(WimgL + (size_t)kc * 65536 + (size_t)bn * 128);
            const uint4* srcL = (const uint4*)(WimgL + (size_t)kc * 65536 + 32768 + (size_t)bn * 128);
            uint4* dstH = (uint4*)(smem + SM_BH);
            uint4* dstL = (uint4*)(smem + SM_BL);
            #pragma unroll
            for (int i = 0; i < 4; i++) {
                dstH[tid + i * 256] = srcH[tid + i * 256];
                dstL[tid + i * 256] = srcL[tid + i * 256];
            }
        }
        __syncthreads();

        #pragma unroll
        for (int ks = 0; ks < 4; ks++) {
            uint32_t ah[2][4], al[2][4];
            {
                int rowa = 32 * wm + (lane & 15);
                int kb = ks * 32 + ((lane >> 4) << 4);
                uint32_t off0 = swz128((uint32_t)(rowa * 128 + kb));
                uint32_t off1 = swz128((uint32_t)((rowa + 16) * 128 + kb));
                ldsm4(ah[0], sb + SM_AH + off0);
                ldsm4(ah[1], sb + SM_AH + off1);
                ldsm4(al[0], sb + SM_AL + off0);
                ldsm4(al[1], sb + SM_AL + off1);
            }
            #pragma unroll
            for (int jp = 0; jp < 4; jp++) {
                int n0 = 64 * wn + 16 * jp;
                int nrow = n0 + ((lane >> 4) << 3) + (lane & 7);
                int kb2 = ks * 32 + (((lane >> 3) & 1) << 4);
                uint32_t offb = swz128((uint32_t)(nrow * 128 + kb2));
                uint32_t bh[4], bl[4];
                ldsm4(bh, sb + SM_BH + offb);
                ldsm4(bl, sb + SM_BL + offb);
                #pragma unroll
                for (int mi = 0; mi < 2; mi++) {
                    #pragma unroll
                    for (int jq = 0; jq < 2; jq++) {
                        float* d = acc[mi][jp * 2 + jq];
                        mma16816(d, ah[mi], bh + 2 * jq);
                        mma16816(d, al[mi], bh + 2 * jq);
                        mma16816(d, ah[mi], bl + 2 * jq);
                    }
                }
            }
        }
        __syncthreads();
    }

    // epilogue: write fp16 (half2 per pair)
    #pragma unroll
    for (int mi = 0; mi < 2; mi++) {
        #pragma unroll
        for (int j = 0; j < 8; j++) {
            int r0 = bm + 32 * wm + 16 * mi + (lane >> 2);
            int c = bn + 64 * wn + 8 * j + (lane & 3) * 2;
            if (r0 < M)
                *(__half2*)(C + (size_t)r0 * HH + c) =
                    __floats2half2_rn(acc[mi][j][0], acc[mi][j][1]);
            int r1 = r0 + 8;
            if (r1 < M)
                *(__half2*)(C + (size_t)r1 * HH + c) =
                    __floats2half2_rn(acc[mi][j][2], acc[mi][j][3]);
        }
    }
}

// ---------------- aggregation: 2 node-slots/block, half2 lanes, named bars ---
// slot = tid>>7 (128 threads each), thread handles 2 channels (half2 = 4B).
// Warp-LDG per gather = 128B (one full line). Slots sync independently via
// named barriers; parity-prefetch hides staging latency.
__global__ __launch_bounds__(256) void k_aggregate(
    const __half* __restrict__ hw, const float* __restrict__ dinv,
    const int* __restrict__ rowptr, const int* __restrict__ csr,
    const float* __restrict__ csrw, const float* __restrict__ bias,
    float* __restrict__ agg, float* __restrict__ sums) {
    const int tid = threadIdx.x;
    const int slot = tid >> 7;           // 0,1
    const int t = tid & 127;
    const int ch = t * 2;
    const int barid = 1 + slot;
    __shared__ int   ssrc[2][2][256];
    __shared__ float sw[2][2][256];
    const float2 bia = *(const float2*)(bias + ch);
    float s0a = 0.f, s1a = 0.f, q0 = 0.f, q1 = 0.f;

    int v = blockIdx.x * 2 + slot;
    const int stride = gridDim.x * 2;
    // prologue: stage first node into parity 0
    if (v < NN) {
        int e0 = rowptr[v];
        int n = min(256, rowptr[v + 1] - e0);
        if (t < n)       { ssrc[slot][0][t] = csr[e0 + t];       sw[slot][0][t] = csrw[e0 + t]; }
        if (t + 128 < n) { ssrc[slot][0][t + 128] = csr[e0 + t + 128];
                           sw[slot][0][t + 128] = csrw[e0 + t + 128]; }
    }
    int p = 0;
    for (; v < NN; v += stride) {
        BAR_SYNC(barid, 128);             // parity p staged for this slot
        // prefetch next node into p^1 (overlaps with gather below)
        int vn = v + stride;
        if (vn < NN) {
            int e0n = rowptr[vn];
            int nn = min(256, rowptr[vn + 1] - e0n);
            if (t < nn)       { ssrc[slot][p ^ 1][t] = csr[e0n + t];
                                sw[slot][p ^ 1][t] = csrw[e0n + t]; }
            if (t + 128 < nn) { ssrc[slot][p ^ 1][t + 128] = csr[e0n + t + 128];
                                sw[slot][p ^ 1][t + 128] = csrw[e0n + t + 128]; }
        }
        const float dv = dinv[v];
        const float dv2 = dv * dv;
        float2 f = __half22float2(*(const __half2*)(hw + (size_t)v * HH + ch));
        float a0 = f.x * dv2, a1 = f.y * dv2;
        const int e0 = rowptr[v], e1 = rowptr[v + 1];
        const int n = min(256, e1 - e0);
        int j = 0;
        for (; j + 8 <= n; j += 8) {
            int i0 = ssrc[slot][p][j + 0], i1 = ssrc[slot][p][j + 1];
            int i2 = ssrc[slot][p][j + 2], i3 = ssrc[slot][p][j + 3];
            int i4 = ssrc[slot][p][j + 4], i5 = ssrc[slot][p][j + 5];
            int i6 = ssrc[slot][p][j + 6], i7 = ssrc[slot][p][j + 7];
            __half2 g0 = *(const __half2*)(hw + (size_t)i0 * HH + ch);
            __half2 g1 = *(const __half2*)(hw + (size_t)i1 * HH + ch);
            __half2 g2 = *(const __half2*)(hw + (size_t)i2 * HH + ch);
            __half2 g3 = *(const __half2*)(hw + (size_t)i3 * HH + ch);
            __half2 g4 = *(const __half2*)(hw + (size_t)i4 * HH + ch);
            __half2 g5 = *(const __half2*)(hw + (size_t)i5 * HH + ch);
            __half2 g6 = *(const __half2*)(hw + (size_t)i6 * HH + ch);
            __half2 g7 = *(const __half2*)(hw + (size_t)i7 * HH + ch);
            float2 f0 = __half22float2(g0), f1 = __half22float2(g1);
            float2 f2 = __half22float2(g2), f3 = __half22float2(g3);
            float2 f4 = __half22float2(g4), f5 = __half22float2(g5);
            float2 f6 = __half22float2(g6), f7 = __half22float2(g7);
            float w0 = sw[slot][p][j + 0], w1 = sw[slot][p][j + 1];
            float w2 = sw[slot][p][j + 2], w3 = sw[slot][p][j + 3];
            float w4 = sw[slot][p][j + 4], w5 = sw[slot][p][j + 5];
            float w6 = sw[slot][p][j + 6], w7 = sw[slot][p][j + 7];
            a0 = fmaf(f0.x, w0, a0); a1 = fmaf(f0.y, w0, a1);
            a0 = fmaf(f1.x, w1, a0); a1 = fmaf(f1.y, w1, a1);
            a0 = fmaf(f2.x, w2, a0); a1 = fmaf(f2.y, w2, a1);
            a0 = fmaf(f3.x, w3, a0); a1 = fmaf(f3.y, w3, a1);
            a0 = fmaf(f4.x, w4, a0); a1 = fmaf(f4.y, w4, a1);
            a0 = fmaf(f5.x, w5, a0); a1 = fmaf(f5.y, w5, a1);
            a0 = fmaf(f6.x, w6, a0); a1 = fmaf(f6.y, w6, a1);
            a0 = fmaf(f7.x, w7, a0); a1 = fmaf(f7.y, w7, a1);
        }
        for (; j < n; j++) {
            float2 g = __half22float2(*(const __half2*)(hw + (size_t)ssrc[slot][p][j] * HH + ch));
            float w = sw[slot][p][j];
            a0 = fmaf(g.x, w, a0);
            a1 = fmaf(g.y, w, a1);
        }
        // rare overflow (degree > 256): 2-bar rhythm reusing parity p
        for (int base = e0 + 256; base < e1; base += 256) {
            BAR_SYNC(barid, 128);
            int n2 = min(256, e1 - base);
            if (t < n2)       { ssrc[slot][p][t] = csr[base + t];
                                sw[slot][p][t] = csrw[base + t]; }
            if (t + 128 < n2) { ssrc[slot][p][t + 128] = csr[base + t + 128];
                                sw[slot][p][t + 128] = csrw[base + t + 128]; }
            BAR_SYNC(barid, 128);
            for (int jj = 0; jj < n2; jj++) {
                float2 g = __half22float2(*(const __half2*)(hw + (size_t)ssrc[slot][p][jj] * HH + ch));
                float w = sw[slot][p][jj];
                a0 = fmaf(g.x, w, a0);
                a1 = fmaf(g.y, w, a1);
            }
        }
        p ^= 1;
        a0 += bia.x;
        a1 += bia.y;
        *(float2*)(agg + (size_t)v * HH + ch) = make_float2(a0, a1);
        s0a += a0; s1a += a1;
        q0 += a0 * a0; q1 += a1 * a1;
    }
    atomicAdd(&sums[ch + 0], s0a);
    atomicAdd(&sums[ch + 1], s1a);
    atomicAdd(&sums[HH + ch + 0], q0);
    atomicAdd(&sums[HH + ch + 1], q1);
}

// ---------------- pooling (fused final BN) + MLP -----------------------------
__global__ void k_pool(const float* __restrict__ agg, const float* __restrict__ hres,
                       const float* __restrict__ sums, const float* __restrict__ bn_g,
                       const float* __restrict__ bn_b, const int* __restrict__ goff,
                       float* __restrict__ pooled) {
    const int gidx = blockIdx.x;
    const int c = threadIdx.x;
    const float inv_n = 1.0f / (float)NN;
    const float mu = sums[c] * inv_n;
    const float var = sums[HH + c] * inv_n - mu * mu;
    const float rg = rsqrtf(var + 1e-5f) * bn_g[c];
    const float bb = bn_b[c];
    const int s = goff[gidx], e = goff[gidx + 1];
    float acc = 0.f;
    for (int r = s; r < e; r++) {
        float val = fmaxf((agg[(size_t)r * HH + c] - mu) * rg + bb, 0.f)
                  + hres[(size_t)r * HH + c];
        acc += val;
    }
    float cnt = (float)(e - s);
    pooled[gidx * HH + c] = acc / fmaxf(cnt, 1.0f);
}

__global__ void k_mlp(const float* __restrict__ pooled,
                      const float* __restrict__ W1, const float* __restrict__ b1,
                      const float* __restrict__ W2, const float* __restrict__ b2,
                      float* __restrict__ out) {
    const int gidx = blockIdx.x;
    const int t = threadIdx.x;  // 128
    __shared__ float sp[HH];
    __shared__ float red[128];
    sp[t] = pooled[gidx * HH + t];
    sp[t + 128] = pooled[gidx * HH + t + 128];
    __syncthreads();
    float acc = b1[t];
    #pragma unroll 8
    for (int k = 0; k < HH; k++) acc += sp[k] * W1[k * 128 + t];
    acc = fmaxf(acc, 0.f);
    red[t] = acc * W2[t];
    __syncthreads();
    for (int off = 64; off > 0; off >>= 1) {
        if (t < off) red[t] += red[t + off];
        __syncthreads();
    }
    if (t == 0) out[gidx] = red[0] + b2[0];
}

// ---------------- launch ----------------------------------------------------
extern "C" void kernel_launch(void* const* d_in, const int* in_sizes, int n_in,
                              void* d_out, int out_size) {
    const int*   x        = (const int*)d_in[0];
    const int*   tags     = (const int*)d_in[1];
    const int*   eidx     = (const int*)d_in[2];
    const int*   batch    = (const int*)d_in[3];
    const float* atom_emb = (const float*)d_in[4];
    const float* tag_emb  = (const float*)d_in[5];
    const float* Wp       = (const float*)d_in[6];
    const float* bp       = (const float*)d_in[7];
    const float* gcn_W    = (const float*)d_in[8];
    const float* gcn_b    = (const float*)d_in[9];
    const float* bn_g     = (const float*)d_in[10];
    const float* bn_b     = (const float*)d_in[11];
    const float* W1       = (const float*)d_in[12];
    const float* b1       = (const float*)d_in[13];
    const float* W2       = (const float*)d_in[14];
    const float* b2       = (const float*)d_in[15];
    float* out = (float*)d_out;

    const int* src = eidx;
    const int* dst = eidx + EE;

    float *bufA, *bufC, *bufD, *dinv, *P, *Q, *sums, *pooled, *csrw;
    __half* hwh;
    int *cnt, *cnt2, *rowptr, *csr, *gcnt, *goff;
    unsigned char* Wimg;
    cudaGetSymbolAddress((void**)&bufA, g_bufA);
    cudaGetSymbolAddress((void**)&hwh, g_hwh);
    cudaGetSymbolAddress((void**)&bufC, g_bufC);
    cudaGetSymbolAddress((void**)&bufD, g_bufD);
    cudaGetSymbolAddress((void**)&cnt, g_cnt);
    cudaGetSymbolAddress((void**)&cnt2, g_cnt2);
    cudaGetSymbolAddress((void**)&rowptr, g_rowptr);
    cudaGetSymbolAddress((void**)&csr, g_csr);
    cudaGetSymbolAddress((void**)&csrw, g_csrw);
    cudaGetSymbolAddress((void**)&gcnt, g_gcnt);
    cudaGetSymbolAddress((void**)&goff, g_goff);
    cudaGetSymbolAddress((void**)&dinv, g_dinv);
    cudaGetSymbolAddress((void**)&P, g_P);
    cudaGetSymbolAddress((void**)&Q, g_Q);
    cudaGetSymbolAddress((void**)&sums, g_sums);
    cudaGetSymbolAddress((void**)&pooled, g_pooled);
    cudaGetSymbolAddress((void**)&Wimg, g_Wimg);

    cudaFuncSetAttribute(k_gemm_mma, cudaFuncAttributeMaxDynamicSharedMemorySize, SM_GEMM);

    const int TB = 256;
    dim3 ggrid(2, (NN + 127) / 128);
    const int AGG_GRID = 2048;

    // launch index 3 = GEMM0 (profiled)
    k_zero_init<<<(NN + TB - 1) / TB, TB>>>(cnt, cnt2, gcnt, sums);
    k_count<<<(EE + TB - 1) / TB, TB>>>(dst, batch, cnt, gcnt);
    k_weights<<<1024 + 103, TB>>>(gcn_W, Wimg, atom_emb, tag_emb, Wp, bp, P, Q);
    k_gemm_mma<<<ggrid, 256, SM_GEMM>>>(nullptr, nullptr, nullptr, nullptr, nullptr,
        Wimg, hwh, NN, P, Q, x, tags, 1, bufA);
    k_scan<<<1, 1024>>>(cnt, rowptr, dinv, gcnt, goff);
    k_fill_csr<<<(EE + TB - 1) / TB, TB>>>(src, dst, rowptr, dinv, cnt2, csr, csrw);

    k_aggregate<<<AGG_GRID, 256>>>(hwh, dinv, rowptr, csr, csrw, gcn_b, bufC, sums);

    float* hres = bufA;
    float* hnew = bufD;
    for (int l = 1; l < LL; l++) {
        k_gemm_mma<<<ggrid, 256, SM_GEMM>>>(
            bufC, hres, sums + (size_t)(l - 1) * 2 * HH,
            bn_g + (size_t)(l - 1) * HH, bn_b + (size_t)(l - 1) * HH,
            Wimg + (size_t)l * 8 * 32768, hwh, NN, P, Q, x, tags, 2, hnew);
        k_aggregate<<<AGG_GRID, 256>>>(hwh, dinv, rowptr, csr, csrw,
                                       gcn_b + (size_t)l * HH, bufC,
                                       sums + (size_t)l * 2 * HH);
        float* tmp = hres; hres = hnew; hnew = tmp;
    }

    k_pool<<<GG, HH>>>(bufC, hres, sums + (size_t)(LL - 1) * 2 * HH,
                       bn_g + (size_t)(LL - 1) * HH, bn_b + (size_t)(LL - 1) * HH,
                       goff, pooled);
    k_mlp<<<GG, 128>>>(pooled, W1, b1, W2, b2, out);
    (void)in_sizes; (void)n_in; (void)out_size;
}

// round 11
// speedup vs baseline: 1.0398x; 1.0398x over previous
#include <cuda_runtime.h>
#include <cuda_bf16.h>
#include <cuda_fp16.h>
#include <math.h>
#include <stdint.h>

#define NN 50000
#define EE 800000
#define GG 512
#define HH 256
#define TT 32
#define LL 4

// ---------------- scratch (device globals) -----------------------------------
__device__ __half g_hA[NN * HH];            // residual h buffer A (fp16)
__device__ __half g_hD[NN * HH];            // residual h buffer D (fp16)
__device__ __half g_hwh[NN * HH];           // GEMM output hw (fp16, gather source)
__device__ __half g_aggh[NN * HH];          // aggregate output (fp16)
__device__ int   g_cnt[NN];
__device__ int   g_cnt2[NN];
__device__ int   g_rowptr[NN + 1];
__device__ int   g_csr[EE];
__device__ float g_csrw[EE];
__device__ int   g_gcnt[GG];
__device__ int   g_goff[GG + 1];
__device__ float g_dinv[NN];
__device__ float g_P[100 * HH];
__device__ float g_Q[3 * HH];
__device__ float g_sums[LL * 2 * HH];
__device__ float g_pooled[GG * HH];
__device__ unsigned char g_Wimg[LL * 4 * 2 * 32768];

// ---------------- helpers ----------------------------------------------------
__device__ __forceinline__ uint32_t smem_u32(const void* p) {
    uint32_t a;
    asm("{ .reg .u64 t; cvta.to.shared.u64 t, %1; cvt.u32.u64 %0, t; }" : "=r"(a) : "l"(p));
    return a;
}
__device__ __forceinline__ uint32_t swz128(uint32_t o) { return o ^ ((o >> 3) & 0x70); }

__device__ __forceinline__ void ldsm4(uint32_t* r, uint32_t addr) {
    asm volatile("ldmatrix.sync.aligned.m8n8.x4.shared.b16 {%0,%1,%2,%3}, [%4];"
        : "=r"(r[0]), "=r"(r[1]), "=r"(r[2]), "=r"(r[3]) : "r"(addr));
}
__device__ __forceinline__ void mma16816(float* d, const uint32_t* a, const uint32_t* b) {
    asm volatile("mma.sync.aligned.m16n8k16.row.col.f32.bf16.bf16.f32 "
        "{%0,%1,%2,%3}, {%4,%5,%6,%7}, {%8,%9}, {%0,%1,%2,%3};"
        : "+f"(d[0]), "+f"(d[1]), "+f"(d[2]), "+f"(d[3])
        : "r"(a[0]), "r"(a[1]), "r"(a[2]), "r"(a[3]), "r"(b[0]), "r"(b[1]));
}
// pack lo-pair into bf16x2 with round-to-nearest
__device__ __forceinline__ uint32_t cvt_bf16x2(float lo, float hi) {
    uint32_t r;
    asm("cvt.rn.bf16x2.f32 %0, %1, %2;" : "=r"(r) : "f"(hi), "f"(lo));
    return r;
}

// ---------------- setup ------------------------------------------------------
__global__ void k_zero_init(int* cnt, int* cnt2, int* gcnt, float* sums) {
    int i = blockIdx.x * blockDim.x + threadIdx.x;
    if (i < NN) { cnt[i] = 0; cnt2[i] = 0; }
    if (i < GG) gcnt[i] = 0;
    if (i < LL * 2 * HH) sums[i] = 0.f;
}

__global__ void k_count(const int* __restrict__ dst, const int* __restrict__ batch,
                        int* cnt, int* gcnt) {
    int e = blockIdx.x * blockDim.x + threadIdx.x;
    if (e < EE) atomicAdd(&cnt[dst[e]], 1);
    if (e < NN) atomicAdd(&gcnt[batch[e]], 1);
}

// ---------------- weights prep ----------------------------------------------
__global__ void k_weights(const float* __restrict__ gcn_W, unsigned char* __restrict__ img,
                          const float* __restrict__ atom_emb, const float* __restrict__ tag_emb,
                          const float* __restrict__ Wp, const float* __restrict__ bp,
                          float* P, float* Q) {
    int bid = blockIdx.x;
    int tid = threadIdx.x;
    if (bid < 1024) {
        int idx = bid * 256 + tid;
        int l = idx >> 16;
        int k = (idx >> 8) & 255;
        int n = idx & 255;
        float w = gcn_W[idx];
        __nv_bfloat16 hi = __float2bfloat16(w);
        __nv_bfloat16 lo = __float2bfloat16(w - __bfloat162float(hi));
        int kc = k >> 6, kk = k & 63;
        uint32_t off = swz128((uint32_t)(n * 128 + kk * 2));
        size_t base = ((size_t)(l * 4 + kc) * 2) * 32768;
        *(__nv_bfloat16*)(img + base + off) = hi;
        *(__nv_bfloat16*)(img + base + 32768 + off) = lo;
    } else {
        int r = bid - 1024;
        int c = tid;
        if (r < 100) {
            float acc = 0.f;
            #pragma unroll 8
            for (int k = 0; k < HH; k++) acc += atom_emb[r * HH + k] * Wp[k * HH + c];
            P[r * HH + c] = acc;
        } else {
            int t = r - 100;
            if (t < 3) {
                float acc = bp[c];
                #pragma unroll
                for (int k = 0; k < TT; k++) acc += tag_emb[t * TT + k] * Wp[(HH + k) * HH + c];
                Q[t * HH + c] = acc;
            }
        }
    }
}

__global__ __launch_bounds__(1024) void k_scan(const int* __restrict__ cnt, int* rowptr,
                                               float* dinv, const int* __restrict__ gcnt,
                                               int* goff) {
    __shared__ int wsum[32];
    const int tid = threadIdx.x;
    const int lane = tid & 31;
    const int w = tid >> 5;
    const int CH = (NN + 1023) / 1024;
    const int beg = tid * CH;
    const int end = min(beg + CH, NN);

    int tot = 0;
    for (int i = beg; i < end; i++) tot += cnt[i];
    int x = tot;
    #pragma unroll
    for (int o = 1; o < 32; o <<= 1) {
        int t = __shfl_up_sync(0xFFFFFFFFu, x, o);
        if (lane >= o) x += t;
    }
    if (lane == 31) wsum[w] = x;
    __syncthreads();
    if (w == 0) {
        int y = wsum[lane];
        #pragma unroll
        for (int o = 1; o < 32; o <<= 1) {
            int t = __shfl_up_sync(0xFFFFFFFFu, y, o);
            if (lane >= o) y += t;
        }
        wsum[lane] = y;
    }
    __syncthreads();
    int run = ((w > 0) ? wsum[w - 1] : 0) + x - tot;
    if (tid == 0) rowptr[0] = 0;
    for (int i = beg; i < end; i++) {
        int cv = cnt[i];
        dinv[i] = rsqrtf((float)cv + 1.0f);
        run += cv;
        rowptr[i + 1] = run;
    }
    __syncthreads();
    int vv = (tid < GG) ? gcnt[tid] : 0;
    int xg = vv;
    #pragma unroll
    for (int o = 1; o < 32; o <<= 1) {
        int t = __shfl_up_sync(0xFFFFFFFFu, xg, o);
        if (lane >= o) xg += t;
    }
    if (lane == 31) wsum[w] = xg;
    __syncthreads();
    if (w == 0) {
        int y = wsum[lane];
        #pragma unroll
        for (int o = 1; o < 32; o <<= 1) {
            int t = __shfl_up_sync(0xFFFFFFFFu, y, o);
            if (lane >= o) y += t;
        }
        wsum[lane] = y;
    }
    __syncthreads();
    int incl = ((w > 0) ? wsum[w - 1] : 0) + xg;
    if (tid == 0) goff[0] = 0;
    if (tid < GG) goff[tid + 1] = incl;
}

__global__ void k_fill_csr(const int* __restrict__ src, const int* __restrict__ dst,
                           const int* __restrict__ rowptr, const float* __restrict__ dinv,
                           int* cnt2, int* csr, float* csrw) {
    int e = blockIdx.x * blockDim.x + threadIdx.x;
    if (e < EE) {
        int s = src[e], d = dst[e];
        int pos = rowptr[d] + atomicAdd(&cnt2[d], 1);
        csr[pos] = s;
        csrw[pos] = dinv[s] * dinv[d];
    }
}

// ---------------- HMMA split-bf16 GEMM with fused prologue -------------------
// mode 1: A = P[x]+Q[tags]; mode 2: A = relu(bn(aggA)) + hres   (aggA,hres fp16)
#define SM_AH 0
#define SM_AL 16384
#define SM_BH 32768
#define SM_BL 49152
#define SM_GEMM 65536

__global__ __launch_bounds__(256, 2) void k_gemm_mma(
    const __half* __restrict__ aggA, const __half* __restrict__ hres,
    const float* __restrict__ sums, const float* __restrict__ bn_g,
    const float* __restrict__ bn_b,
    const unsigned char* __restrict__ WimgL,
    __half* __restrict__ C, int M,
    const float* __restrict__ P, const float* __restrict__ Q,
    const int* __restrict__ x, const int* __restrict__ tags,
    int mode, __half* __restrict__ Aout) {
    extern __shared__ char smem[];
    const int tid = threadIdx.x;
    const int wid = tid >> 5;
    const int lane = tid & 31;
    const int wm = wid & 3;
    const int wn = wid >> 2;
    const uint32_t sb = smem_u32(smem);
    const int bm = blockIdx.y * 128;
    const int bn = blockIdx.x * 128;
    const int c4 = (tid & 15) << 2;
    const bool do_write_a = (blockIdx.x == 0);

    float acc[2][8][4];
    #pragma unroll
    for (int mi = 0; mi < 2; mi++)
        #pragma unroll
        for (int j = 0; j < 8; j++)
            #pragma unroll
            for (int q = 0; q < 4; q++) acc[mi][j][q] = 0.f;

    const float inv_n = 1.0f / (float)NN;

    for (int kc = 0; kc < 4; kc++) {
        const int col = kc * 64 + c4;
        float mu0 = 0.f, mu1 = 0.f, mu2 = 0.f, mu3 = 0.f;
        float rg0 = 0.f, rg1 = 0.f, rg2 = 0.f, rg3 = 0.f;
        float bb0 = 0.f, bb1 = 0.f, bb2 = 0.f, bb3 = 0.f;
        if (mode == 2) {
            mu0 = sums[col + 0] * inv_n;
            mu1 = sums[col + 1] * inv_n;
            mu2 = sums[col + 2] * inv_n;
            mu3 = sums[col + 3] * inv_n;
            float v0 = sums[HH + col + 0] * inv_n - mu0 * mu0;
            float v1 = sums[HH + col + 1] * inv_n - mu1 * mu1;
            float v2 = sums[HH + col + 2] * inv_n - mu2 * mu2;
            float v3 = sums[HH + col + 3] * inv_n - mu3 * mu3;
            rg0 = rsqrtf(v0 + 1e-5f) * bn_g[col + 0];
            rg1 = rsqrtf(v1 + 1e-5f) * bn_g[col + 1];
            rg2 = rsqrtf(v2 + 1e-5f) * bn_g[col + 2];
            rg3 = rsqrtf(v3 + 1e-5f) * bn_g[col + 3];
            bb0 = bn_b[col + 0];
            bb1 = bn_b[col + 1];
            bb2 = bn_b[col + 2];
            bb3 = bn_b[col + 3];
        }
        #pragma unroll
        for (int i = 0; i < 8; i++) {
            int r = (tid >> 4) + i * 16;
            int gr = bm + r;
            float4 v = make_float4(0.f, 0.f, 0.f, 0.f);
            if (gr < M) {
                if (mode == 1) {
                    int xi = x[gr], tg = tags[gr];
                    float4 p = *(const float4*)(P + (size_t)xi * HH + col);
                    float4 q = *(const float4*)(Q + (size_t)tg * HH + col);
                    v = make_float4(p.x + q.x, p.y + q.y, p.z + q.z, p.w + q.w);
                } else {
                    uint2 au = *(const uint2*)(aggA + (size_t)gr * HH + col);
                    uint2 ru = *(const uint2*)(hres + (size_t)gr * HH + col);
                    float2 a01 = __half22float2(*(const __half2*)&au.x);
                    float2 a23 = __half22float2(*(const __half2*)&au.y);
                    float2 r01 = __half22float2(*(const __half2*)&ru.x);
                    float2 r23 = __half22float2(*(const __half2*)&ru.y);
                    v.x = fmaxf((a01.x - mu0) * rg0 + bb0, 0.f) + r01.x;
                    v.y = fmaxf((a01.y - mu1) * rg1 + bb1, 0.f) + r01.y;
                    v.z = fmaxf((a23.x - mu2) * rg2 + bb2, 0.f) + r23.x;
                    v.w = fmaxf((a23.y - mu3) * rg3 + bb3, 0.f) + r23.y;
                }
                if (do_write_a) {
                    uint2 ho;
                    *(__half2*)&ho.x = __floats2half2_rn(v.x, v.y);
                    *(__half2*)&ho.y = __floats2half2_rn(v.z, v.w);
                    *(uint2*)(Aout + (size_t)gr * HH + col) = ho;
                }
            }
            // truncation split: hi = top 16 bits (PRMT); lo = v - hi (bf16 rn)
            uint32_t ax = __float_as_uint(v.x), ay = __float_as_uint(v.y);
            uint32_t az = __float_as_uint(v.z), aw = __float_as_uint(v.w);
            uint2 hv = make_uint2(__byte_perm(ax, ay, 0x7632),
                                  __byte_perm(az, aw, 0x7632));
            float lx = v.x - __uint_as_float(ax & 0xFFFF0000u);
            float ly = v.y - __uint_as_float(ay & 0xFFFF0000u);
            float lz = v.z - __uint_as_float(az & 0xFFFF0000u);
            float lw = v.w - __uint_as_float(aw & 0xFFFF0000u);
            uint2 lv = make_uint2(cvt_bf16x2(lx, ly), cvt_bf16x2(lz, lw));
            uint32_t off = swz128((uint32_t)(r * 128 + c4 * 2));
            *(uint2*)(smem + SM_AH + off) = hv;
            *(uint2*)(smem + SM_AL + off) = lv;
        }
        {
            const uint4* srcH = (const uint4*)(WimgL + (size_t)kc * 65536 + (size_t)bn * 128);
            const uint4* srcL = (const uint4*)(WimgL + (size_t)kc * 65536 + 32768 + (size_t)bn * 128);
            uint4* dstH = (uint4*)(smem + SM_BH);
            uint4* dstL = (uint4*)(smem + SM_BL);
            #pragma unroll
            for (int i = 0; i < 4; i++) {
                dstH[tid + i * 256] = srcH[tid + i * 256];
                dstL[tid + i * 256] = srcL[tid + i * 256];
            }
        }
        __syncthreads();

        #pragma unroll
        for (int ks = 0; ks < 4; ks++) {
            uint32_t ah[2][4], al[2][4];
            {
                int rowa = 32 * wm + (lane & 15);
                int kb = ks * 32 + ((lane >> 4) << 4);
                uint32_t off0 = swz128((uint32_t)(rowa * 128 + kb));
                uint32_t off1 = swz128((uint32_t)((rowa + 16) * 128 + kb));
                ldsm4(ah[0], sb + SM_AH + off0);
                ldsm4(ah[1], sb + SM_AH + off1);
                ldsm4(al[0], sb + SM_AL + off0);
                ldsm4(al[1], sb + SM_AL + off1);
            }
            #pragma unroll
            for (int jp = 0; jp < 4; jp++) {
                int n0 = 64 * wn + 16 * jp;
                int nrow = n0 + ((lane >> 4) << 3) + (lane & 7);
                int kb2 = ks * 32 + (((lane >> 3) & 1) << 4);
                uint32_t offb = swz128((uint32_t)(nrow * 128 + kb2));
                uint32_t bh[4], bl[4];
                ldsm4(bh, sb + SM_BH + offb);
                ldsm4(bl, sb + SM_BL + offb);
                #pragma unroll
                for (int mi = 0; mi < 2; mi++) {
                    #pragma unroll
                    for (int jq = 0; jq < 2; jq++) {
                        float* d = acc[mi][jp * 2 + jq];
                        mma16816(d, ah[mi], bh + 2 * jq);
                        mma16816(d, al[mi], bh + 2 * jq);
                        mma16816(d, ah[mi], bl + 2 * jq);
                    }
                }
            }
        }
        __syncthreads();
    }

    // epilogue: write fp16 (half2 per pair)
    #pragma unroll
    for (int mi = 0; mi < 2; mi++) {
        #pragma unroll
        for (int j = 0; j < 8; j++) {
            int r0 = bm + 32 * wm + 16 * mi + (lane >> 2);
            int c = bn + 64 * wn + 8 * j + (lane & 3) * 2;
            if (r0 < M)
                *(__half2*)(C + (size_t)r0 * HH + c) =
                    __floats2half2_rn(acc[mi][j][0], acc[mi][j][1]);
            int r1 = r0 + 8;
            if (r1 < M)
                *(__half2*)(C + (size_t)r1 * HH + c) =
                    __floats2half2_rn(acc[mi][j][2], acc[mi][j][3]);
        }
    }
}

// ---------------- aggregation (R9-proven: parity prefetch, 8-wide batch) -----
__global__ __launch_bounds__(256) void k_aggregate(
    const __half* __restrict__ hw, const float* __restrict__ dinv,
    const int* __restrict__ rowptr, const int* __restrict__ csr,
    const float* __restrict__ csrw, const float* __restrict__ bias,
    __half* __restrict__ agg, float* __restrict__ sums) {
    const int c = threadIdx.x;
    const float bia = bias[c];
    const __half* __restrict__ hwc = hw + c;
    float s = 0.f, s2 = 0.f;
    __shared__ int   ssrc[2][256];
    __shared__ float sw[2][256];

    {
        int v0 = blockIdx.x;
        if (v0 < NN) {
            int s0 = rowptr[v0];
            int n = min(256, rowptr[v0 + 1] - s0);
            if (c < n) { ssrc[0][c] = csr[s0 + c]; sw[0][c] = csrw[s0 + c]; }
        }
    }
    int p = 0;
    for (int v = blockIdx.x; v < NN; v += gridDim.x) {
        __syncthreads();
        int vn = v + gridDim.x;
        if (vn < NN) {
            int s0n = rowptr[vn];
            int nn = min(256, rowptr[vn + 1] - s0n);
            if (c < nn) { ssrc[p ^ 1][c] = csr[s0n + c]; sw[p ^ 1][c] = csrw[s0n + c]; }
        }
        const float dv = dinv[v];
        float acc = __half2float(hwc[(size_t)v * HH]) * dv * dv;
        const int s0 = rowptr[v], s1 = rowptr[v + 1];
        const int n = min(256, s1 - s0);
        int j = 0;
        for (; j + 8 <= n; j += 8) {
            int i0 = ssrc[p][j + 0], i1 = ssrc[p][j + 1];
            int i2 = ssrc[p][j + 2], i3 = ssrc[p][j + 3];
            int i4 = ssrc[p][j + 4], i5 = ssrc[p][j + 5];
            int i6 = ssrc[p][j + 6], i7 = ssrc[p][j + 7];
            __half t0 = hwc[(size_t)i0 * HH];
            __half t1 = hwc[(size_t)i1 * HH];
            __half t2 = hwc[(size_t)i2 * HH];
            __half t3 = hwc[(size_t)i3 * HH];
            __half t4 = hwc[(size_t)i4 * HH];
            __half t5 = hwc[(size_t)i5 * HH];
            __half t6 = hwc[(size_t)i6 * HH];
            __half t7 = hwc[(size_t)i7 * HH];
            acc = fmaf(__half2float(t0), sw[p][j + 0], acc);
            acc = fmaf(__half2float(t1), sw[p][j + 1], acc);
            acc = fmaf(__half2float(t2), sw[p][j + 2], acc);
            acc = fmaf(__half2float(t3), sw[p][j + 3], acc);
            acc = fmaf(__half2float(t4), sw[p][j + 4], acc);
            acc = fmaf(__half2float(t5), sw[p][j + 5], acc);
            acc = fmaf(__half2float(t6), sw[p][j + 6], acc);
            acc = fmaf(__half2float(t7), sw[p][j + 7], acc);
        }
        for (; j < n; j++)
            acc = fmaf(__half2float(hwc[(size_t)ssrc[p][j] * HH]), sw[p][j], acc);
        for (int base = s0 + 256; base < s1; base += 256) {
            __syncthreads();
            int n2 = min(256, s1 - base);
            if (c < n2) { ssrc[p][c] = csr[base + c]; sw[p][c] = csrw[base + c]; }
            __syncthreads();
            for (int jj = 0; jj < n2; jj++)
                acc = fmaf(__half2float(hwc[(size_t)ssrc[p][jj] * HH]), sw[p][jj], acc);
        }
        p ^= 1;
        float val = acc + bia;
        agg[(size_t)v * HH + c] = __float2half_rn(val);
        s += val;
        s2 += val * val;
    }
    atomicAdd(&sums[c], s);
    atomicAdd(&sums[HH + c], s2);
}

// ---------------- pooling (fused final BN) + MLP -----------------------------
__global__ void k_pool(const __half* __restrict__ agg, const __half* __restrict__ hres,
                       const float* __restrict__ sums, const float* __restrict__ bn_g,
                       const float* __restrict__ bn_b, const int* __restrict__ goff,
                       float* __restrict__ pooled) {
    const int gidx = blockIdx.x;
    const int c = threadIdx.x;
    const float inv_n = 1.0f / (float)NN;
    const float mu = sums[c] * inv_n;
    const float var = sums[HH + c] * inv_n - mu * mu;
    const float rg = rsqrtf(var + 1e-5f) * bn_g[c];
    const float bb = bn_b[c];
    const int s = goff[gidx], e = goff[gidx + 1];
    float acc = 0.f;
    for (int r = s; r < e; r++) {
        float val = fmaxf((__half2float(agg[(size_t)r * HH + c]) - mu) * rg + bb, 0.f)
                  + __half2float(hres[(size_t)r * HH + c]);
        acc += val;
    }
    float cnt = (float)(e - s);
    pooled[gidx * HH + c] = acc / fmaxf(cnt, 1.0f);
}

__global__ void k_mlp(const float* __restrict__ pooled,
                      const float* __restrict__ W1, const float* __restrict__ b1,
                      const float* __restrict__ W2, const float* __restrict__ b2,
                      float* __restrict__ out) {
    const int gidx = blockIdx.x;
    const int t = threadIdx.x;  // 128
    __shared__ float sp[HH];
    __shared__ float red[128];
    sp[t] = pooled[gidx * HH + t];
    sp[t + 128] = pooled[gidx * HH + t + 128];
    __syncthreads();
    float acc = b1[t];
    #pragma unroll 8
    for (int k = 0; k < HH; k++) acc += sp[k] * W1[k * 128 + t];
    acc = fmaxf(acc, 0.f);
    red[t] = acc * W2[t];
    __syncthreads();
    for (int off = 64; off > 0; off >>= 1) {
        if (t < off) red[t] += red[t + off];
        __syncthreads();
    }
    if (t == 0) out[gidx] = red[0] + b2[0];
}

// ---------------- launch ----------------------------------------------------
extern "C" void kernel_launch(void* const* d_in, const int* in_sizes, int n_in,
                              void* d_out, int out_size) {
    const int*   x        = (const int*)d_in[0];
    const int*   tags     = (const int*)d_in[1];
    const int*   eidx     = (const int*)d_in[2];
    const int*   batch    = (const int*)d_in[3];
    const float* atom_emb = (const float*)d_in[4];
    const float* tag_emb  = (const float*)d_in[5];
    const float* Wp       = (const float*)d_in[6];
    const float* bp       = (const float*)d_in[7];
    const float* gcn_W    = (const float*)d_in[8];
    const float* gcn_b    = (const float*)d_in[9];
    const float* bn_g     = (const float*)d_in[10];
    const float* bn_b     = (const float*)d_in[11];
    const float* W1       = (const float*)d_in[12];
    const float* b1       = (const float*)d_in[13];
    const float* W2       = (const float*)d_in[14];
    const float* b2       = (const float*)d_in[15];
    float* out = (float*)d_out;

    const int* src = eidx;
    const int* dst = eidx + EE;

    float *dinv, *P, *Q, *sums, *pooled, *csrw;
    __half *hA, *hD, *hwh, *aggh;
    int *cnt, *cnt2, *rowptr, *csr, *gcnt, *goff;
    unsigned char* Wimg;
    cudaGetSymbolAddress((void**)&hA, g_hA);
    cudaGetSymbolAddress((void**)&hD, g_hD);
    cudaGetSymbolAddress((void**)&hwh, g_hwh);
    cudaGetSymbolAddress((void**)&aggh, g_aggh);
    cudaGetSymbolAddress((void**)&cnt, g_cnt);
    cudaGetSymbolAddress((void**)&cnt2, g_cnt2);
    cudaGetSymbolAddress((void**)&rowptr, g_rowptr);
    cudaGetSymbolAddress((void**)&csr, g_csr);
    cudaGetSymbolAddress((void**)&csrw, g_csrw);
    cudaGetSymbolAddress((void**)&gcnt, g_gcnt);
    cudaGetSymbolAddress((void**)&goff, g_goff);
    cudaGetSymbolAddress((void**)&dinv, g_dinv);
    cudaGetSymbolAddress((void**)&P, g_P);
    cudaGetSymbolAddress((void**)&Q, g_Q);
    cudaGetSymbolAddress((void**)&sums, g_sums);
    cudaGetSymbolAddress((void**)&pooled, g_pooled);
    cudaGetSymbolAddress((void**)&Wimg, g_Wimg);

    cudaFuncSetAttribute(k_gemm_mma, cudaFuncAttributeMaxDynamicSharedMemorySize, SM_GEMM);

    const int TB = 256;
    dim3 ggrid(2, (NN + 127) / 128);
    const int AGG_GRID = 2048;

    // launch index 3 = GEMM0 (profiled)
    k_zero_init<<<(NN + TB - 1) / TB, TB>>>(cnt, cnt2, gcnt, sums);
    k_count<<<(EE + TB - 1) / TB, TB>>>(dst, batch, cnt, gcnt);
    k_weights<<<1024 + 103, TB>>>(gcn_W, Wimg, atom_emb, tag_emb, Wp, bp, P, Q);
    k_gemm_mma<<<ggrid, 256, SM_GEMM>>>(nullptr, nullptr, nullptr, nullptr, nullptr,
        Wimg, hwh, NN, P, Q, x, tags, 1, hA);
    k_scan<<<1, 1024>>>(cnt, rowptr, dinv, gcnt, goff);
    k_fill_csr<<<(EE + TB - 1) / TB, TB>>>(src, dst, rowptr, dinv, cnt2, csr, csrw);

    k_aggregate<<<AGG_GRID, 256>>>(hwh, dinv, rowptr, csr, csrw, gcn_b, aggh, sums);

    __half* hres = hA;
    __half* hnew = hD;
    for (int l = 1; l < LL; l++) {
        k_gemm_mma<<<ggrid, 256, SM_GEMM>>>(
            aggh, hres, sums + (size_t)(l - 1) * 2 * HH,
            bn_g + (size_t)(l - 1) * HH, bn_b + (size_t)(l - 1) * HH,
            Wimg + (size_t)l * 8 * 32768, hwh, NN, P, Q, x, tags, 2, hnew);
        k_aggregate<<<AGG_GRID, 256>>>(hwh, dinv, rowptr, csr, csrw,
                                       gcn_b + (size_t)l * HH, aggh,
                                       sums + (size_t)l * 2 * HH);
        __half* tmp = hres; hres = hnew; hnew = tmp;
    }

    k_pool<<<GG, HH>>>(aggh, hres, sums + (size_t)(LL - 1) * 2 * HH,
                       bn_g + (size_t)(LL - 1) * HH, bn_b + (size_t)(LL - 1) * HH,
                       goff, pooled);
    k_mlp<<<GG, 128>>>(pooled, W1, b1, W2, b2, out);
    (void)in_sizes; (void)n_in; (void)out_size;
}

// round 12
// speedup vs baseline: 1.1002x; 1.0581x over previous
#include <cuda_runtime.h>
#include <cuda_fp16.h>
#include <math.h>
#include <stdint.h>

#define NN 50000
#define EE 800000
#define GG 512
#define HH 256
#define TT 32
#define LL 4

// ---------------- scratch (device globals) -----------------------------------
__device__ __half g_hA[NN * HH];            // residual h buffer A (fp16)
__device__ __half g_hD[NN * HH];            // residual h buffer D (fp16)
__device__ __half g_hwh[NN * HH];           // GEMM output hw (fp16, gather source)
__device__ __half g_aggh[NN * HH];          // aggregate output (fp16)
__device__ int   g_cnt[NN];
__device__ int   g_cnt2[NN];
__device__ int   g_rowptr[NN + 1];
__device__ int   g_csr[EE];
__device__ float g_csrw[EE];
__device__ int   g_gcnt[GG];
__device__ int   g_goff[GG + 1];
__device__ float g_dinv[NN];
__device__ float g_P[100 * HH];
__device__ float g_Q[3 * HH];
__device__ float g_sums[LL * 2 * HH];
__device__ float g_pooled[GG * HH];
// fp16 hi/lo images of W^T: [L][kc=4][split=2][32768B] = 1MB
__device__ unsigned char g_Wimg[LL * 4 * 2 * 32768];

// ---------------- helpers ----------------------------------------------------
__device__ __forceinline__ uint32_t smem_u32(const void* p) {
    uint32_t a;
    asm("{ .reg .u64 t; cvta.to.shared.u64 t, %1; cvt.u32.u64 %0, t; }" : "=r"(a) : "l"(p));
    return a;
}
__device__ __forceinline__ uint32_t swz128(uint32_t o) { return o ^ ((o >> 3) & 0x70); }

__device__ __forceinline__ void ldsm4(uint32_t* r, uint32_t addr) {
    asm volatile("ldmatrix.sync.aligned.m8n8.x4.shared.b16 {%0,%1,%2,%3}, [%4];"
        : "=r"(r[0]), "=r"(r[1]), "=r"(r[2]), "=r"(r[3]) : "r"(addr));
}
__device__ __forceinline__ void mma_f16(float* d, const uint32_t* a, const uint32_t* b) {
    asm volatile("mma.sync.aligned.m16n8k16.row.col.f32.f16.f16.f32 "
        "{%0,%1,%2,%3}, {%4,%5,%6,%7}, {%8,%9}, {%0,%1,%2,%3};"
        : "+f"(d[0]), "+f"(d[1]), "+f"(d[2]), "+f"(d[3])
        : "r"(a[0]), "r"(a[1]), "r"(a[2]), "r"(a[3]), "r"(b[0]), "r"(b[1]));
}
__device__ __forceinline__ uint32_t cvt_f16x2(float lo, float hi) {
    uint32_t r;
    asm("cvt.rn.f16x2.f32 %0, %1, %2;" : "=r"(r) : "f"(hi), "f"(lo));
    return r;
}

// ---------------- fused: counting + W fp16-hi/lo images + proj tables --------
__global__ void k_count_weights(const int* __restrict__ dst, const int* __restrict__ batch,
                                int* cnt, int* gcnt,
                                const float* __restrict__ gcn_W, unsigned char* __restrict__ img,
                                const float* __restrict__ atom_emb,
                                const float* __restrict__ tag_emb,
                                const float* __restrict__ Wp, const float* __restrict__ bp,
                                float* P, float* Q) {
    int bid = blockIdx.x;
    int tid = threadIdx.x;
    if (bid < 3125) {
        int e = bid * 256 + tid;
        if (e < EE) atomicAdd(&cnt[dst[e]], 1);
        if (e < NN) atomicAdd(&gcnt[batch[e]], 1);
    } else if (bid < 3125 + 1024) {
        int idx = (bid - 3125) * 256 + tid;
        int l = idx >> 16;
        int k = (idx >> 8) & 255;
        int n = idx & 255;
        float w = gcn_W[idx];
        __half hi = __float2half(w);
        __half lo = __float2half(w - __half2float(hi));
        int kc = k >> 6, kk = k & 63;
        uint32_t off = swz128((uint32_t)(n * 128 + kk * 2));
        size_t base = ((size_t)(l * 4 + kc) * 2) * 32768;
        *(__half*)(img + base + off) = hi;
        *(__half*)(img + base + 32768 + off) = lo;
    } else {
        int r = bid - 3125 - 1024;
        int c = tid;
        if (r < 100) {
            float acc = 0.f;
            #pragma unroll 8
            for (int k = 0; k < HH; k++) acc += atom_emb[r * HH + k] * Wp[k * HH + c];
            P[r * HH + c] = acc;
        } else {
            int t = r - 100;
            if (t < 3) {
                float acc = bp[c];
                #pragma unroll
                for (int k = 0; k < TT; k++) acc += tag_emb[t * TT + k] * Wp[(HH + k) * HH + c];
                Q[t * HH + c] = acc;
            }
        }
    }
}

__global__ __launch_bounds__(1024) void k_scan(const int* __restrict__ cnt, int* rowptr,
                                               float* dinv, const int* __restrict__ gcnt,
                                               int* goff) {
    __shared__ int wsum[32];
    const int tid = threadIdx.x;
    const int lane = tid & 31;
    const int w = tid >> 5;
    const int CH = (NN + 1023) / 1024;
    const int beg = tid * CH;
    const int end = min(beg + CH, NN);

    int tot = 0;
    for (int i = beg; i < end; i++) tot += cnt[i];
    int x = tot;
    #pragma unroll
    for (int o = 1; o < 32; o <<= 1) {
        int t = __shfl_up_sync(0xFFFFFFFFu, x, o);
        if (lane >= o) x += t;
    }
    if (lane == 31) wsum[w] = x;
    __syncthreads();
    if (w == 0) {
        int y = wsum[lane];
        #pragma unroll
        for (int o = 1; o < 32; o <<= 1) {
            int t = __shfl_up_sync(0xFFFFFFFFu, y, o);
            if (lane >= o) y += t;
        }
        wsum[lane] = y;
    }
    __syncthreads();
    int run = ((w > 0) ? wsum[w - 1] : 0) + x - tot;
    if (tid == 0) rowptr[0] = 0;
    for (int i = beg; i < end; i++) {
        int cv = cnt[i];
        dinv[i] = rsqrtf((float)cv + 1.0f);
        run += cv;
        rowptr[i + 1] = run;
    }
    __syncthreads();
    int vv = (tid < GG) ? gcnt[tid] : 0;
    int xg = vv;
    #pragma unroll
    for (int o = 1; o < 32; o <<= 1) {
        int t = __shfl_up_sync(0xFFFFFFFFu, xg, o);
        if (lane >= o) xg += t;
    }
    if (lane == 31) wsum[w] = xg;
    __syncthreads();
    if (w == 0) {
        int y = wsum[lane];
        #pragma unroll
        for (int o = 1; o < 32; o <<= 1) {
            int t = __shfl_up_sync(0xFFFFFFFFu, y, o);
            if (lane >= o) y += t;
        }
        wsum[lane] = y;
    }
    __syncthreads();
    int incl = ((w > 0) ? wsum[w - 1] : 0) + xg;
    if (tid == 0) goff[0] = 0;
    if (tid < GG) goff[tid + 1] = incl;
}

// ---------------- HMMA fp16 GEMM (A single fp16, W hi/lo fp16) ---------------
// Fused CSR fill: blocks with blockIdx.y >= GY_GEMM run fill_csr (mode-1 launch only).
#define SM_A  0
#define SM_BH 16384
#define SM_BL 32768
#define SM_GEMM 49152
#define GY_GEMM 391

__global__ __launch_bounds__(256, 2) void k_gemm_mma(
    const __half* __restrict__ aggA, const __half* __restrict__ hres,
    const float* __restrict__ sums, const float* __restrict__ bn_g,
    const float* __restrict__ bn_b,
    const unsigned char* __restrict__ WimgL,
    __half* __restrict__ C, int M,
    const float* __restrict__ P, const float* __restrict__ Q,
    const int* __restrict__ x, const int* __restrict__ tags,
    int mode, __half* __restrict__ Aout,
    const int* __restrict__ esrc, const int* __restrict__ edst,
    const int* __restrict__ rowptr, const float* __restrict__ dinv,
    int* cnt2, int* csr, float* csrw) {
    extern __shared__ char smem[];
    const int tid = threadIdx.x;

    if (blockIdx.y >= GY_GEMM) {                 // fused fill_csr blocks
        int e = ((blockIdx.y - GY_GEMM) * 2 + blockIdx.x) * 256 + tid;
        if (e < EE) {
            int s = esrc[e], d = edst[e];
            int pos = rowptr[d] + atomicAdd(&cnt2[d], 1);
            csr[pos] = s;
            csrw[pos] = dinv[s] * dinv[d];
        }
        return;
    }

    const int wid = tid >> 5;
    const int lane = tid & 31;
    const int wm = wid & 3;
    const int wn = wid >> 2;
    const uint32_t sb = smem_u32(smem);
    const int bm = blockIdx.y * 128;
    const int bn = blockIdx.x * 128;
    const int c4 = (tid & 15) << 2;
    const bool do_write_a = (blockIdx.x == 0);

    float acc[2][8][4];
    #pragma unroll
    for (int mi = 0; mi < 2; mi++)
        #pragma unroll
        for (int j = 0; j < 8; j++)
            #pragma unroll
            for (int q = 0; q < 4; q++) acc[mi][j][q] = 0.f;

    const float inv_n = 1.0f / (float)NN;

    for (int kc = 0; kc < 4; kc++) {
        const int col = kc * 64 + c4;
        float mu0 = 0.f, mu1 = 0.f, mu2 = 0.f, mu3 = 0.f;
        float rg0 = 0.f, rg1 = 0.f, rg2 = 0.f, rg3 = 0.f;
        float bb0 = 0.f, bb1 = 0.f, bb2 = 0.f, bb3 = 0.f;
        if (mode == 2) {
            mu0 = sums[col + 0] * inv_n;
            mu1 = sums[col + 1] * inv_n;
            mu2 = sums[col + 2] * inv_n;
            mu3 = sums[col + 3] * inv_n;
            float v0 = sums[HH + col + 0] * inv_n - mu0 * mu0;
            float v1 = sums[HH + col + 1] * inv_n - mu1 * mu1;
            float v2 = sums[HH + col + 2] * inv_n - mu2 * mu2;
            float v3 = sums[HH + col + 3] * inv_n - mu3 * mu3;
            rg0 = rsqrtf(v0 + 1e-5f) * bn_g[col + 0];
            rg1 = rsqrtf(v1 + 1e-5f) * bn_g[col + 1];
            rg2 = rsqrtf(v2 + 1e-5f) * bn_g[col + 2];
            rg3 = rsqrtf(v3 + 1e-5f) * bn_g[col + 3];
            bb0 = bn_b[col + 0];
            bb1 = bn_b[col + 1];
            bb2 = bn_b[col + 2];
            bb3 = bn_b[col + 3];
        }
        #pragma unroll
        for (int i = 0; i < 8; i++) {
            int r = (tid >> 4) + i * 16;
            int gr = bm + r;
            float4 v = make_float4(0.f, 0.f, 0.f, 0.f);
            if (gr < M) {
                if (mode == 1) {
                    int xi = x[gr], tg = tags[gr];
                    float4 p = *(const float4*)(P + (size_t)xi * HH + col);
                    float4 q = *(const float4*)(Q + (size_t)tg * HH + col);
                    v = make_float4(p.x + q.x, p.y + q.y, p.z + q.z, p.w + q.w);
                } else {
                    uint2 au = *(const uint2*)(aggA + (size_t)gr * HH + col);
                    uint2 ru = *(const uint2*)(hres + (size_t)gr * HH + col);
                    float2 a01 = __half22float2(*(const __half2*)&au.x);
                    float2 a23 = __half22float2(*(const __half2*)&au.y);
                    float2 r01 = __half22float2(*(const __half2*)&ru.x);
                    float2 r23 = __half22float2(*(const __half2*)&ru.y);
                    v.x = fmaxf((a01.x - mu0) * rg0 + bb0, 0.f) + r01.x;
                    v.y = fmaxf((a01.y - mu1) * rg1 + bb1, 0.f) + r01.y;
                    v.z = fmaxf((a23.x - mu2) * rg2 + bb2, 0.f) + r23.x;
                    v.w = fmaxf((a23.y - mu3) * rg3 + bb3, 0.f) + r23.y;
                }
            }
            uint2 hv = make_uint2(cvt_f16x2(v.x, v.y), cvt_f16x2(v.z, v.w));
            if (gr < M && do_write_a)
                *(uint2*)(Aout + (size_t)gr * HH + col) = hv;
            uint32_t off = swz128((uint32_t)(r * 128 + c4 * 2));
            *(uint2*)(smem + SM_A + off) = hv;
        }
        {
            const uint4* srcH = (const uint4*)(WimgL + (size_t)kc * 65536 + (size_t)bn * 128);
            const uint4* srcL = (const uint4*)(WimgL + (size_t)kc * 65536 + 32768 + (size_t)bn * 128);
            uint4* dstH = (uint4*)(smem + SM_BH);
            uint4* dstL = (uint4*)(smem + SM_BL);
            #pragma unroll
            for (int i = 0; i < 4; i++) {
                dstH[tid + i * 256] = srcH[tid + i * 256];
                dstL[tid + i * 256] = srcL[tid + i * 256];
            }
        }
        __syncthreads();

        #pragma unroll
        for (int ks = 0; ks < 4; ks++) {
            uint32_t ah[2][4];
            {
                int rowa = 32 * wm + (lane & 15);
                int kb = ks * 32 + ((lane >> 4) << 4);
                uint32_t off0 = swz128((uint32_t)(rowa * 128 + kb));
                uint32_t off1 = swz128((uint32_t)((rowa + 16) * 128 + kb));
                ldsm4(ah[0], sb + SM_A + off0);
                ldsm4(ah[1], sb + SM_A + off1);
            }
            #pragma unroll
            for (int jp = 0; jp < 4; jp++) {
                int n0 = 64 * wn + 16 * jp;
                int nrow = n0 + ((lane >> 4) << 3) + (lane & 7);
                int kb2 = ks * 32 + (((lane >> 3) & 1) << 4);
                uint32_t offb = swz128((uint32_t)(nrow * 128 + kb2));
                uint32_t bh[4], bl[4];
                ldsm4(bh, sb + SM_BH + offb);
                ldsm4(bl, sb + SM_BL + offb);
                #pragma unroll
                for (int mi = 0; mi < 2; mi++) {
                    #pragma unroll
                    for (int jq = 0; jq < 2; jq++) {
                        float* d = acc[mi][jp * 2 + jq];
                        mma_f16(d, ah[mi], bh + 2 * jq);
                        mma_f16(d, ah[mi], bl + 2 * jq);
                    }
                }
            }
        }
        __syncthreads();
    }

    #pragma unroll
    for (int mi = 0; mi < 2; mi++) {
        #pragma unroll
        for (int j = 0; j < 8; j++) {
            int r0 = bm + 32 * wm + 16 * mi + (lane >> 2);
            int c = bn + 64 * wn + 8 * j + (lane & 3) * 2;
            if (r0 < M)
                *(__half2*)(C + (size_t)r0 * HH + c) =
                    __floats2half2_rn(acc[mi][j][0], acc[mi][j][1]);
            int r1 = r0 + 8;
            if (r1 < M)
                *(__half2*)(C + (size_t)r1 * HH + c) =
                    __floats2half2_rn(acc[mi][j][2], acc[mi][j][3]);
        }
    }
}

// ---------------- aggregation (R9 structure, fp16 in/out) --------------------
__global__ __launch_bounds__(256) void k_aggregate(
    const __half* __restrict__ hw, const float* __restrict__ dinv,
    const int* __restrict__ rowptr, const int* __restrict__ csr,
    const float* __restrict__ csrw, const float* __restrict__ bias,
    __half* __restrict__ agg, float* __restrict__ sums) {
    const int c = threadIdx.x;
    const float bia = bias[c];
    const __half* __restrict__ hwc = hw + c;
    float s = 0.f, s2 = 0.f;
    __shared__ int   ssrc[2][256];
    __shared__ float sw[2][256];

    {
        int v0 = blockIdx.x;
        if (v0 < NN) {
            int s0 = rowptr[v0];
            int n = min(256, rowptr[v0 + 1] - s0);
            if (c < n) { ssrc[0][c] = csr[s0 + c]; sw[0][c] = csrw[s0 + c]; }
        }
    }
    int p = 0;
    for (int v = blockIdx.x; v < NN; v += gridDim.x) {
        __syncthreads();
        int vn = v + gridDim.x;
        if (vn < NN) {
            int s0n = rowptr[vn];
            int nn = min(256, rowptr[vn + 1] - s0n);
            if (c < nn) { ssrc[p ^ 1][c] = csr[s0n + c]; sw[p ^ 1][c] = csrw[s0n + c]; }
        }
        const float dv = dinv[v];
        float acc = __half2float(hwc[(size_t)v * HH]) * dv * dv;
        const int s0 = rowptr[v], s1 = rowptr[v + 1];
        const int n = min(256, s1 - s0);
        int j = 0;
        for (; j + 8 <= n; j += 8) {
            int i0 = ssrc[p][j + 0], i1 = ssrc[p][j + 1];
            int i2 = ssrc[p][j + 2], i3 = ssrc[p][j + 3];
            int i4 = ssrc[p][j + 4], i5 = ssrc[p][j + 5];
            int i6 = ssrc[p][j + 6], i7 = ssrc[p][j + 7];
            __half t0 = hwc[(size_t)i0 * HH];
            __half t1 = hwc[(size_t)i1 * HH];
            __half t2 = hwc[(size_t)i2 * HH];
            __half t3 = hwc[(size_t)i3 * HH];
            __half t4 = hwc[(size_t)i4 * HH];
            __half t5 = hwc[(size_t)i5 * HH];
            __half t6 = hwc[(size_t)i6 * HH];
            __half t7 = hwc[(size_t)i7 * HH];
            acc = fmaf(__half2float(t0), sw[p][j + 0], acc);
            acc = fmaf(__half2float(t1), sw[p][j + 1], acc);
            acc = fmaf(__half2float(t2), sw[p][j + 2], acc);
            acc = fmaf(__half2float(t3), sw[p][j + 3], acc);
            acc = fmaf(__half2float(t4), sw[p][j + 4], acc);
            acc = fmaf(__half2float(t5), sw[p][j + 5], acc);
            acc = fmaf(__half2float(t6), sw[p][j + 6], acc);
            acc = fmaf(__half2float(t7), sw[p][j + 7], acc);
        }
        for (; j < n; j++)
            acc = fmaf(__half2float(hwc[(size_t)ssrc[p][j] * HH]), sw[p][j], acc);
        for (int base = s0 + 256; base < s1; base += 256) {
            __syncthreads();
            int n2 = min(256, s1 - base);
            if (c < n2) { ssrc[p][c] = csr[base + c]; sw[p][c] = csrw[base + c]; }
            __syncthreads();
            for (int jj = 0; jj < n2; jj++)
                acc = fmaf(__half2float(hwc[(size_t)ssrc[p][jj] * HH]), sw[p][jj], acc);
        }
        p ^= 1;
        float val = acc + bia;
        agg[(size_t)v * HH + c] = __float2half_rn(val);
        s += val;
        s2 += val * val;
    }
    atomicAdd(&sums[c], s);
    atomicAdd(&sums[HH + c], s2);
}

// ---------------- pooling (fused final BN) + MLP -----------------------------
__global__ void k_pool(const __half* __restrict__ agg, const __half* __restrict__ hres,
                       const float* __restrict__ sums, const float* __restrict__ bn_g,
                       const float* __restrict__ bn_b, const int* __restrict__ goff,
                       float* __restrict__ pooled) {
    const int gidx = blockIdx.x;
    const int c = threadIdx.x;
    const float inv_n = 1.0f / (float)NN;
    const float mu = sums[c] * inv_n;
    const float var = sums[HH + c] * inv_n - mu * mu;
    const float rg = rsqrtf(var + 1e-5f) * bn_g[c];
    const float bb = bn_b[c];
    const int s = goff[gidx], e = goff[gidx + 1];
    float acc = 0.f;
    for (int r = s; r < e; r++) {
        float val = fmaxf((__half2float(agg[(size_t)r * HH + c]) - mu) * rg + bb, 0.f)
                  + __half2float(hres[(size_t)r * HH + c]);
        acc += val;
    }
    float cnt = (float)(e - s);
    pooled[gidx * HH + c] = acc / fmaxf(cnt, 1.0f);
}

__global__ void k_mlp(const float* __restrict__ pooled,
                      const float* __restrict__ W1, const float* __restrict__ b1,
                      const float* __restrict__ W2, const float* __restrict__ b2,
                      float* __restrict__ out) {
    const int gidx = blockIdx.x;
    const int t = threadIdx.x;  // 128
    __shared__ float sp[HH];
    __shared__ float red[128];
    sp[t] = pooled[gidx * HH + t];
    sp[t + 128] = pooled[gidx * HH + t + 128];
    __syncthreads();
    float acc = b1[t];
    #pragma unroll 8
    for (int k = 0; k < HH; k++) acc += sp[k] * W1[k * 128 + t];
    acc = fmaxf(acc, 0.f);
    red[t] = acc * W2[t];
    __syncthreads();
    for (int off = 64; off > 0; off >>= 1) {
        if (t < off) red[t] += red[t + off];
        __syncthreads();
    }
    if (t == 0) out[gidx] = red[0] + b2[0];
}

// ---------------- launch ----------------------------------------------------
extern "C" void kernel_launch(void* const* d_in, const int* in_sizes, int n_in,
                              void* d_out, int out_size) {
    const int*   x        = (const int*)d_in[0];
    const int*   tags     = (const int*)d_in[1];
    const int*   eidx     = (const int*)d_in[2];
    const int*   batch    = (const int*)d_in[3];
    const float* atom_emb = (const float*)d_in[4];
    const float* tag_emb  = (const float*)d_in[5];
    const float* Wp       = (const float*)d_in[6];
    const float* bp       = (const float*)d_in[7];
    const float* gcn_W    = (const float*)d_in[8];
    const float* gcn_b    = (const float*)d_in[9];
    const float* bn_g     = (const float*)d_in[10];
    const float* bn_b     = (const float*)d_in[11];
    const float* W1       = (const float*)d_in[12];
    const float* b1       = (const float*)d_in[13];
    const float* W2       = (const float*)d_in[14];
    const float* b2       = (const float*)d_in[15];
    float* out = (float*)d_out;

    const int* src = eidx;
    const int* dst = eidx + EE;

    float *dinv, *P, *Q, *sums, *pooled, *csrw;
    __half *hA, *hD, *hwh, *aggh;
    int *cnt, *cnt2, *rowptr, *csr, *gcnt, *goff;
    unsigned char* Wimg;
    cudaGetSymbolAddress((void**)&hA, g_hA);
    cudaGetSymbolAddress((void**)&hD, g_hD);
    cudaGetSymbolAddress((void**)&hwh, g_hwh);
    cudaGetSymbolAddress((void**)&aggh, g_aggh);
    cudaGetSymbolAddress((void**)&cnt, g_cnt);
    cudaGetSymbolAddress((void**)&cnt2, g_cnt2);
    cudaGetSymbolAddress((void**)&rowptr, g_rowptr);
    cudaGetSymbolAddress((void**)&csr, g_csr);
    cudaGetSymbolAddress((void**)&csrw, g_csrw);
    cudaGetSymbolAddress((void**)&gcnt, g_gcnt);
    cudaGetSymbolAddress((void**)&goff, g_goff);
    cudaGetSymbolAddress((void**)&dinv, g_dinv);
    cudaGetSymbolAddress((void**)&P, g_P);
    cudaGetSymbolAddress((void**)&Q, g_Q);
    cudaGetSymbolAddress((void**)&sums, g_sums);
    cudaGetSymbolAddress((void**)&pooled, g_pooled);
    cudaGetSymbolAddress((void**)&Wimg, g_Wimg);

    cudaFuncSetAttribute(k_gemm_mma, cudaFuncAttributeMaxDynamicSharedMemorySize, SM_GEMM);

    const int TB = 256;
    const int AGG_GRID = 2048;

    // zero via memset nodes (not kernel launches)
    cudaMemsetAsync(cnt, 0, NN * sizeof(int));
    cudaMemsetAsync(cnt2, 0, NN * sizeof(int));
    cudaMemsetAsync(gcnt, 0, GG * sizeof(int));
    cudaMemsetAsync(sums, 0, LL * 2 * HH * sizeof(float));

    // launch 0: counting + weight images + projection tables
    k_count_weights<<<3125 + 1024 + 103, TB>>>(dst, batch, cnt, gcnt,
                                               gcn_W, Wimg, atom_emb, tag_emb, Wp, bp, P, Q);
    // launch 1: scans (rowptr, dinv, goff)
    k_scan<<<1, 1024>>>(cnt, rowptr, dinv, gcnt, goff);
    // launch 2: GEMM0 (embed-fused) + fused fill_csr in extra blocks
    {
        dim3 g0(2, GY_GEMM + 1563);
        k_gemm_mma<<<g0, 256, SM_GEMM>>>(nullptr, nullptr, nullptr, nullptr, nullptr,
            Wimg, hwh, NN, P, Q, x, tags, 1, hA,
            src, dst, rowptr, dinv, cnt2, csr, csrw);
    }
    // launch 3: aggregate (PROFILED)
    k_aggregate<<<AGG_GRID, 256>>>(hwh, dinv, rowptr, csr, csrw, gcn_b, aggh, sums);

    __half* hres = hA;
    __half* hnew = hD;
    dim3 ggrid(2, GY_GEMM);
    for (int l = 1; l < LL; l++) {
        k_gemm_mma<<<ggrid, 256, SM_GEMM>>>(
            aggh, hres, sums + (size_t)(l - 1) * 2 * HH,
            bn_g + (size_t)(l - 1) * HH, bn_b + (size_t)(l - 1) * HH,
            Wimg + (size_t)l * 8 * 32768, hwh, NN, P, Q, x, tags, 2, hnew,
            src, dst, rowptr, dinv, cnt2, csr, csrw);
        k_aggregate<<<AGG_GRID, 256>>>(hwh, dinv, rowptr, csr, csrw,
                                       gcn_b + (size_t)l * HH, aggh,
                                       sums + (size_t)l * 2 * HH);
        __half* tmp = hres; hres = hnew; hnew = tmp;
    }

    k_pool<<<GG, HH>>>(aggh, hres, sums + (size_t)(LL - 1) * 2 * HH,
                       bn_g + (size_t)(LL - 1) * HH, bn_b + (size_t)(LL - 1) * HH,
                       goff, pooled);
    k_mlp<<<GG, 128>>>(pooled, W1, b1, W2, b2, out);
    (void)in_sizes; (void)n_in; (void)out_size;
}

// round 13
// speedup vs baseline: 1.1480x; 1.0434x over previous
#include <cuda_runtime.h>
#include <cuda_fp16.h>
#include <math.h>
#include <stdint.h>

#define NN 50000
#define EE 800000
#define GG 512
#define HH 256
#define TT 32
#define LL 4

// ---------------- scratch (device globals) -----------------------------------
__device__ __half g_hA[NN * HH];            // residual h buffer A (fp16)
__device__ __half g_hD[NN * HH];            // residual h buffer D (fp16)
__device__ __half g_hwh[NN * HH];           // GEMM output hw (fp16, gather source)
__device__ __half g_aggh[NN * HH];          // aggregate output (fp16)
__device__ int   g_cnt[NN];
__device__ int   g_cnt2[NN];
__device__ int   g_rowptr[NN + 1];
__device__ int2  g_csre[EE];                // packed (src index, weight bits)
__device__ int   g_gcnt[GG];
__device__ int   g_goff[GG + 1];
__device__ float g_dinv[NN];
__device__ float g_P[100 * HH];
__device__ float g_Q[3 * HH];
__device__ float g_sums[LL * 2 * HH];
__device__ float g_pooled[GG * HH];
// fp16 hi/lo images of W^T: [L][kc=4][split=2][32768B] = 1MB
__device__ unsigned char g_Wimg[LL * 4 * 2 * 32768];

// ---------------- helpers ----------------------------------------------------
__device__ __forceinline__ uint32_t smem_u32(const void* p) {
    uint32_t a;
    asm("{ .reg .u64 t; cvta.to.shared.u64 t, %1; cvt.u32.u64 %0, t; }" : "=r"(a) : "l"(p));
    return a;
}
__device__ __forceinline__ uint32_t swz128(uint32_t o) { return o ^ ((o >> 3) & 0x70); }

__device__ __forceinline__ void ldsm4(uint32_t* r, uint32_t addr) {
    asm volatile("ldmatrix.sync.aligned.m8n8.x4.shared.b16 {%0,%1,%2,%3}, [%4];"
        : "=r"(r[0]), "=r"(r[1]), "=r"(r[2]), "=r"(r[3]) : "r"(addr));
}
__device__ __forceinline__ void mma_f16(float* d, const uint32_t* a, const uint32_t* b) {
    asm volatile("mma.sync.aligned.m16n8k16.row.col.f32.f16.f16.f32 "
        "{%0,%1,%2,%3}, {%4,%5,%6,%7}, {%8,%9}, {%0,%1,%2,%3};"
        : "+f"(d[0]), "+f"(d[1]), "+f"(d[2]), "+f"(d[3])
        : "r"(a[0]), "r"(a[1]), "r"(a[2]), "r"(a[3]), "r"(b[0]), "r"(b[1]));
}
__device__ __forceinline__ uint32_t cvt_f16x2(float lo, float hi) {
    uint32_t r;
    asm("cvt.rn.f16x2.f32 %0, %1, %2;" : "=r"(r) : "f"(hi), "f"(lo));
    return r;
}

// ---------------- fused: counting + W fp16-hi/lo images + proj tables --------
__global__ void k_count_weights(const int* __restrict__ dst, const int* __restrict__ batch,
                                int* cnt, int* gcnt,
                                const float* __restrict__ gcn_W, unsigned char* __restrict__ img,
                                const float* __restrict__ atom_emb,
                                const float* __restrict__ tag_emb,
                                const float* __restrict__ Wp, const float* __restrict__ bp,
                                float* P, float* Q) {
    int bid = blockIdx.x;
    int tid = threadIdx.x;
    if (bid < 3125) {
        int e = bid * 256 + tid;
        if (e < EE) atomicAdd(&cnt[dst[e]], 1);
        if (e < NN) atomicAdd(&gcnt[batch[e]], 1);
    } else if (bid < 3125 + 1024) {
        int idx = (bid - 3125) * 256 + tid;
        int l = idx >> 16;
        int k = (idx >> 8) & 255;
        int n = idx & 255;
        float w = gcn_W[idx];
        __half hi = __float2half(w);
        __half lo = __float2half(w - __half2float(hi));
        int kc = k >> 6, kk = k & 63;
        uint32_t off = swz128((uint32_t)(n * 128 + kk * 2));
        size_t base = ((size_t)(l * 4 + kc) * 2) * 32768;
        *(__half*)(img + base + off) = hi;
        *(__half*)(img + base + 32768 + off) = lo;
    } else {
        int r = bid - 3125 - 1024;
        int c = tid;
        if (r < 100) {
            float acc = 0.f;
            #pragma unroll 8
            for (int k = 0; k < HH; k++) acc += atom_emb[r * HH + k] * Wp[k * HH + c];
            P[r * HH + c] = acc;
        } else {
            int t = r - 100;
            if (t < 3) {
                float acc = bp[c];
                #pragma unroll
                for (int k = 0; k < TT; k++) acc += tag_emb[t * TT + k] * Wp[(HH + k) * HH + c];
                Q[t * HH + c] = acc;
            }
        }
    }
}

__global__ __launch_bounds__(1024) void k_scan(const int* __restrict__ cnt, int* rowptr,
                                               float* dinv, const int* __restrict__ gcnt,
                                               int* goff) {
    __shared__ int wsum[32];
    const int tid = threadIdx.x;
    const int lane = tid & 31;
    const int w = tid >> 5;
    const int CH = (NN + 1023) / 1024;
    const int beg = tid * CH;
    const int end = min(beg + CH, NN);

    int tot = 0;
    for (int i = beg; i < end; i++) tot += cnt[i];
    int x = tot;
    #pragma unroll
    for (int o = 1; o < 32; o <<= 1) {
        int t = __shfl_up_sync(0xFFFFFFFFu, x, o);
        if (lane >= o) x += t;
    }
    if (lane == 31) wsum[w] = x;
    __syncthreads();
    if (w == 0) {
        int y = wsum[lane];
        #pragma unroll
        for (int o = 1; o < 32; o <<= 1) {
            int t = __shfl_up_sync(0xFFFFFFFFu, y, o);
            if (lane >= o) y += t;
        }
        wsum[lane] = y;
    }
    __syncthreads();
    int run = ((w > 0) ? wsum[w - 1] : 0) + x - tot;
    if (tid == 0) rowptr[0] = 0;
    for (int i = beg; i < end; i++) {
        int cv = cnt[i];
        dinv[i] = rsqrtf((float)cv + 1.0f);
        run += cv;
        rowptr[i + 1] = run;
    }
    __syncthreads();
    int vv = (tid < GG) ? gcnt[tid] : 0;
    int xg = vv;
    #pragma unroll
    for (int o = 1; o < 32; o <<= 1) {
        int t = __shfl_up_sync(0xFFFFFFFFu, xg, o);
        if (lane >= o) xg += t;
    }
    if (lane == 31) wsum[w] = xg;
    __syncthreads();
    if (w == 0) {
        int y = wsum[lane];
        #pragma unroll
        for (int o = 1; o < 32; o <<= 1) {
            int t = __shfl_up_sync(0xFFFFFFFFu, y, o);
            if (lane >= o) y += t;
        }
        wsum[lane] = y;
    }
    __syncthreads();
    int incl = ((w > 0) ? wsum[w - 1] : 0) + xg;
    if (tid == 0) goff[0] = 0;
    if (tid < GG) goff[tid + 1] = incl;
}

// ---------------- HMMA fp16 GEMM (A single fp16, W hi/lo fp16) ---------------
// Fused CSR fill: blocks with blockIdx.y >= GY_GEMM run fill_csr (mode-1 launch only).
#define SM_A  0
#define SM_BH 16384
#define SM_BL 32768
#define SM_GEMM 49152
#define GY_GEMM 391

__global__ __launch_bounds__(256, 2) void k_gemm_mma(
    const __half* __restrict__ aggA, const __half* __restrict__ hres,
    const float* __restrict__ sums, const float* __restrict__ bn_g,
    const float* __restrict__ bn_b,
    const unsigned char* __restrict__ WimgL,
    __half* __restrict__ C, int M,
    const float* __restrict__ P, const float* __restrict__ Q,
    const int* __restrict__ x, const int* __restrict__ tags,
    int mode, __half* __restrict__ Aout,
    const int* __restrict__ esrc, const int* __restrict__ edst,
    const int* __restrict__ rowptr, const float* __restrict__ dinv,
    int* cnt2, int2* csre) {
    extern __shared__ char smem[];
    const int tid = threadIdx.x;

    if (blockIdx.y >= GY_GEMM) {                 // fused fill_csr blocks
        int e = ((blockIdx.y - GY_GEMM) * 2 + blockIdx.x) * 256 + tid;
        if (e < EE) {
            int s = esrc[e], d = edst[e];
            int pos = rowptr[d] + atomicAdd(&cnt2[d], 1);
            csre[pos] = make_int2(s, __float_as_int(dinv[s] * dinv[d]));
        }
        return;
    }

    const int wid = tid >> 5;
    const int lane = tid & 31;
    const int wm = wid & 3;
    const int wn = wid >> 2;
    const uint32_t sb = smem_u32(smem);
    const int bm = blockIdx.y * 128;
    const int bn = blockIdx.x * 128;
    const int c4 = (tid & 15) << 2;
    const bool do_write_a = (blockIdx.x == 0);

    float acc[2][8][4];
    #pragma unroll
    for (int mi = 0; mi < 2; mi++)
        #pragma unroll
        for (int j = 0; j < 8; j++)
            #pragma unroll
            for (int q = 0; q < 4; q++) acc[mi][j][q] = 0.f;

    const float inv_n = 1.0f / (float)NN;

    for (int kc = 0; kc < 4; kc++) {
        const int col = kc * 64 + c4;
        float mu0 = 0.f, mu1 = 0.f, mu2 = 0.f, mu3 = 0.f;
        float rg0 = 0.f, rg1 = 0.f, rg2 = 0.f, rg3 = 0.f;
        float bb0 = 0.f, bb1 = 0.f, bb2 = 0.f, bb3 = 0.f;
        if (mode == 2) {
            mu0 = sums[col + 0] * inv_n;
            mu1 = sums[col + 1] * inv_n;
            mu2 = sums[col + 2] * inv_n;
            mu3 = sums[col + 3] * inv_n;
            float v0 = sums[HH + col + 0] * inv_n - mu0 * mu0;
            float v1 = sums[HH + col + 1] * inv_n - mu1 * mu1;
            float v2 = sums[HH + col + 2] * inv_n - mu2 * mu2;
            float v3 = sums[HH + col + 3] * inv_n - mu3 * mu3;
            rg0 = rsqrtf(v0 + 1e-5f) * bn_g[col + 0];
            rg1 = rsqrtf(v1 + 1e-5f) * bn_g[col + 1];
            rg2 = rsqrtf(v2 + 1e-5f) * bn_g[col + 2];
            rg3 = rsqrtf(v3 + 1e-5f) * bn_g[col + 3];
            bb0 = bn_b[col + 0];
            bb1 = bn_b[col + 1];
            bb2 = bn_b[col + 2];
            bb3 = bn_b[col + 3];
        }
        #pragma unroll
        for (int i = 0; i < 8; i++) {
            int r = (tid >> 4) + i * 16;
            int gr = bm + r;
            float4 v = make_float4(0.f, 0.f, 0.f, 0.f);
            if (gr < M) {
                if (mode == 1) {
                    int xi = x[gr], tg = tags[gr];
                    float4 p = *(const float4*)(P + (size_t)xi * HH + col);
                    float4 q = *(const float4*)(Q + (size_t)tg * HH + col);
                    v = make_float4(p.x + q.x, p.y + q.y, p.z + q.z, p.w + q.w);
                } else {
                    uint2 au = *(const uint2*)(aggA + (size_t)gr * HH + col);
                    uint2 ru = *(const uint2*)(hres + (size_t)gr * HH + col);
                    float2 a01 = __half22float2(*(const __half2*)&au.x);
                    float2 a23 = __half22float2(*(const __half2*)&au.y);
                    float2 r01 = __half22float2(*(const __half2*)&ru.x);
                    float2 r23 = __half22float2(*(const __half2*)&ru.y);
                    v.x = fmaxf((a01.x - mu0) * rg0 + bb0, 0.f) + r01.x;
                    v.y = fmaxf((a01.y - mu1) * rg1 + bb1, 0.f) + r01.y;
                    v.z = fmaxf((a23.x - mu2) * rg2 + bb2, 0.f) + r23.x;
                    v.w = fmaxf((a23.y - mu3) * rg3 + bb3, 0.f) + r23.y;
                }
            }
            uint2 hv = make_uint2(cvt_f16x2(v.x, v.y), cvt_f16x2(v.z, v.w));
            if (gr < M && do_write_a)
                *(uint2*)(Aout + (size_t)gr * HH + col) = hv;
            uint32_t off = swz128((uint32_t)(r * 128 + c4 * 2));
            *(uint2*)(smem + SM_A + off) = hv;
        }
        {
            const uint4* srcH = (const uint4*)(WimgL + (size_t)kc * 65536 + (size_t)bn * 128);
            const uint4* srcL = (const uint4*)(WimgL + (size_t)kc * 65536 + 32768 + (size_t)bn * 128);
            uint4* dstH = (uint4*)(smem + SM_BH);
            uint4* dstL = (uint4*)(smem + SM_BL);
            #pragma unroll
            for (int i = 0; i < 4; i++) {
                dstH[tid + i * 256] = srcH[tid + i * 256];
                dstL[tid + i * 256] = srcL[tid + i * 256];
            }
        }
        __syncthreads();

        #pragma unroll
        for (int ks = 0; ks < 4; ks++) {
            uint32_t ah[2][4];
            {
                int rowa = 32 * wm + (lane & 15);
                int kb = ks * 32 + ((lane >> 4) << 4);
                uint32_t off0 = swz128((uint32_t)(rowa * 128 + kb));
                uint32_t off1 = swz128((uint32_t)((rowa + 16) * 128 + kb));
                ldsm4(ah[0], sb + SM_A + off0);
                ldsm4(ah[1], sb + SM_A + off1);
            }
            #pragma unroll
            for (int jp = 0; jp < 4; jp++) {
                int n0 = 64 * wn + 16 * jp;
                int nrow = n0 + ((lane >> 4) << 3) + (lane & 7);
                int kb2 = ks * 32 + (((lane >> 3) & 1) << 4);
                uint32_t offb = swz128((uint32_t)(nrow * 128 + kb2));
                uint32_t bh[4], bl[4];
                ldsm4(bh, sb + SM_BH + offb);
                ldsm4(bl, sb + SM_BL + offb);
                #pragma unroll
                for (int mi = 0; mi < 2; mi++) {
                    #pragma unroll
                    for (int jq = 0; jq < 2; jq++) {
                        float* d = acc[mi][jp * 2 + jq];
                        mma_f16(d, ah[mi], bh + 2 * jq);
                        mma_f16(d, ah[mi], bl + 2 * jq);
                    }
                }
            }
        }
        __syncthreads();
    }

    #pragma unroll
    for (int mi = 0; mi < 2; mi++) {
        #pragma unroll
        for (int j = 0; j < 8; j++) {
            int r0 = bm + 32 * wm + 16 * mi + (lane >> 2);
            int c = bn + 64 * wn + 8 * j + (lane & 3) * 2;
            if (r0 < M)
                *(__half2*)(C + (size_t)r0 * HH + c) =
                    __floats2half2_rn(acc[mi][j][0], acc[mi][j][1]);
            int r1 = r0 + 8;
            if (r1 < M)
                *(__half2*)(C + (size_t)r1 * HH + c) =
                    __floats2half2_rn(acc[mi][j][2], acc[mi][j][3]);
        }
    }
}

// ---------------- aggregation: 128 thr/node, half2 lanes, int2 edges ---------
// Per edge per warp: 1 LDS.64 (packed idx+weight) + 1 LDG.32 (half2, 128B/warp).
__global__ __launch_bounds__(128) void k_aggregate(
    const __half* __restrict__ hw, const float* __restrict__ dinv,
    const int* __restrict__ rowptr, const int2* __restrict__ csre,
    const float* __restrict__ bias, __half* __restrict__ agg,
    float* __restrict__ sums) {
    const int t = threadIdx.x;           // 0..127
    const int ch = t * 2;
    const float2 bia = *(const float2*)(bias + ch);
    float s0a = 0.f, s1a = 0.f, q0 = 0.f, q1 = 0.f;
    __shared__ int2 se[2][256];

    {
        int v0 = blockIdx.x;
        if (v0 < NN) {
            int e0 = rowptr[v0];
            int n = min(256, rowptr[v0 + 1] - e0);
            if (t < n) se[0][t] = csre[e0 + t];
            if (t + 128 < n) se[0][t + 128] = csre[e0 + t + 128];
        }
    }
    int p = 0;
    for (int v = blockIdx.x; v < NN; v += gridDim.x) {
        __syncthreads();
        int vn = v + gridDim.x;
        if (vn < NN) {
            int e0n = rowptr[vn];
            int nn = min(256, rowptr[vn + 1] - e0n);
            if (t < nn) se[p ^ 1][t] = csre[e0n + t];
            if (t + 128 < nn) se[p ^ 1][t + 128] = csre[e0n + t + 128];
        }
        const float dv = dinv[v];
        const float dv2 = dv * dv;
        float2 f = __half22float2(*(const __half2*)(hw + (size_t)v * HH + ch));
        float a0 = f.x * dv2, a1 = f.y * dv2;
        const int e0 = rowptr[v], e1 = rowptr[v + 1];
        const int n = min(256, e1 - e0);
        int j = 0;
        for (; j + 8 <= n; j += 8) {
            int2 x0 = se[p][j + 0], x1 = se[p][j + 1];
            int2 x2 = se[p][j + 2], x3 = se[p][j + 3];
            int2 x4 = se[p][j + 4], x5 = se[p][j + 5];
            int2 x6 = se[p][j + 6], x7 = se[p][j + 7];
            __half2 g0 = *(const __half2*)(hw + (size_t)x0.x * HH + ch);
            __half2 g1 = *(const __half2*)(hw + (size_t)x1.x * HH + ch);
            __half2 g2 = *(const __half2*)(hw + (size_t)x2.x * HH + ch);
            __half2 g3 = *(const __half2*)(hw + (size_t)x3.x * HH + ch);
            __half2 g4 = *(const __half2*)(hw + (size_t)x4.x * HH + ch);
            __half2 g5 = *(const __half2*)(hw + (size_t)x5.x * HH + ch);
            __half2 g6 = *(const __half2*)(hw + (size_t)x6.x * HH + ch);
            __half2 g7 = *(const __half2*)(hw + (size_t)x7.x * HH + ch);
            float2 f0 = __half22float2(g0), f1 = __half22float2(g1);
            float2 f2 = __half22float2(g2), f3 = __half22float2(g3);
            float2 f4 = __half22float2(g4), f5 = __half22float2(g5);
            float2 f6 = __half22float2(g6), f7 = __half22float2(g7);
            float w0 = __int_as_float(x0.y), w1 = __int_as_float(x1.y);
            float w2 = __int_as_float(x2.y), w3 = __int_as_float(x3.y);
            float w4 = __int_as_float(x4.y), w5 = __int_as_float(x5.y);
            float w6 = __int_as_float(x6.y), w7 = __int_as_float(x7.y);
            a0 = fmaf(f0.x, w0, a0); a1 = fmaf(f0.y, w0, a1);
            a0 = fmaf(f1.x, w1, a0); a1 = fmaf(f1.y, w1, a1);
            a0 = fmaf(f2.x, w2, a0); a1 = fmaf(f2.y, w2, a1);
            a0 = fmaf(f3.x, w3, a0); a1 = fmaf(f3.y, w3, a1);
            a0 = fmaf(f4.x, w4, a0); a1 = fmaf(f4.y, w4, a1);
            a0 = fmaf(f5.x, w5, a0); a1 = fmaf(f5.y, w5, a1);
            a0 = fmaf(f6.x, w6, a0); a1 = fmaf(f6.y, w6, a1);
            a0 = fmaf(f7.x, w7, a0); a1 = fmaf(f7.y, w7, a1);
        }
        for (; j < n; j++) {
            int2 xx = se[p][j];
            float2 g = __half22float2(*(const __half2*)(hw + (size_t)xx.x * HH + ch));
            float w = __int_as_float(xx.y);
            a0 = fmaf(g.x, w, a0);
            a1 = fmaf(g.y, w, a1);
        }
        // rare overflow (degree > 256): 2-sync rhythm reusing parity p
        for (int base = e0 + 256; base < e1; base += 256) {
            __syncthreads();
            int n2 = min(256, e1 - base);
            if (t < n2) se[p][t] = csre[base + t];
            if (t + 128 < n2) se[p][t + 128] = csre[base + t + 128];
            __syncthreads();
            for (int jj = 0; jj < n2; jj++) {
                int2 xx = se[p][jj];
                float2 g = __half22float2(*(const __half2*)(hw + (size_t)xx.x * HH + ch));
                float w = __int_as_float(xx.y);
                a0 = fmaf(g.x, w, a0);
                a1 = fmaf(g.y, w, a1);
            }
        }
        p ^= 1;
        a0 += bia.x;
        a1 += bia.y;
        *(__half2*)(agg + (size_t)v * HH + ch) = __floats2half2_rn(a0, a1);
        s0a += a0; s1a += a1;
        q0 += a0 * a0; q1 += a1 * a1;
    }
    atomicAdd(&sums[ch + 0], s0a);
    atomicAdd(&sums[ch + 1], s1a);
    atomicAdd(&sums[HH + ch + 0], q0);
    atomicAdd(&sums[HH + ch + 1], q1);
}

// ---------------- pooling (fused final BN) + MLP -----------------------------
__global__ void k_pool(const __half* __restrict__ agg, const __half* __restrict__ hres,
                       const float* __restrict__ sums, const float* __restrict__ bn_g,
                       const float* __restrict__ bn_b, const int* __restrict__ goff,
                       float* __restrict__ pooled) {
    const int gidx = blockIdx.x;
    const int c = threadIdx.x;
    const float inv_n = 1.0f / (float)NN;
    const float mu = sums[c] * inv_n;
    const float var = sums[HH + c] * inv_n - mu * mu;
    const float rg = rsqrtf(var + 1e-5f) * bn_g[c];
    const float bb = bn_b[c];
    const int s = goff[gidx], e = goff[gidx + 1];
    float acc = 0.f;
    for (int r = s; r < e; r++) {
        float val = fmaxf((__half2float(agg[(size_t)r * HH + c]) - mu) * rg + bb, 0.f)
                  + __half2float(hres[(size_t)r * HH + c]);
        acc += val;
    }
    float cnt = (float)(e - s);
    pooled[gidx * HH + c] = acc / fmaxf(cnt, 1.0f);
}

__global__ void k_mlp(const float* __restrict__ pooled,
                      const float* __restrict__ W1, const float* __restrict__ b1,
                      const float* __restrict__ W2, const float* __restrict__ b2,
                      float* __restrict__ out) {
    const int gidx = blockIdx.x;
    const int t = threadIdx.x;  // 128
    __shared__ float sp[HH];
    __shared__ float red[128];
    sp[t] = pooled[gidx * HH + t];
    sp[t + 128] = pooled[gidx * HH + t + 128];
    __syncthreads();
    float acc = b1[t];
    #pragma unroll 8
    for (int k = 0; k < HH; k++) acc += sp[k] * W1[k * 128 + t];
    acc = fmaxf(acc, 0.f);
    red[t] = acc * W2[t];
    __syncthreads();
    for (int off = 64; off > 0; off >>= 1) {
        if (t < off) red[t] += red[t + off];
        __syncthreads();
    }
    if (t == 0) out[gidx] = red[0] + b2[0];
}

// ---------------- launch ----------------------------------------------------
extern "C" void kernel_launch(void* const* d_in, const int* in_sizes, int n_in,
                              void* d_out, int out_size) {
    const int*   x        = (const int*)d_in[0];
    const int*   tags     = (const int*)d_in[1];
    const int*   eidx     = (const int*)d_in[2];
    const int*   batch    = (const int*)d_in[3];
    const float* atom_emb = (const float*)d_in[4];
    const float* tag_emb  = (const float*)d_in[5];
    const float* Wp       = (const float*)d_in[6];
    const float* bp       = (const float*)d_in[7];
    const float* gcn_W    = (const float*)d_in[8];
    const float* gcn_b    = (const float*)d_in[9];
    const float* bn_g     = (const float*)d_in[10];
    const float* bn_b     = (const float*)d_in[11];
    const float* W1       = (const float*)d_in[12];
    const float* b1       = (const float*)d_in[13];
    const float* W2       = (const float*)d_in[14];
    const float* b2       = (const float*)d_in[15];
    float* out = (float*)d_out;

    const int* src = eidx;
    const int* dst = eidx + EE;

    float *dinv, *P, *Q, *sums, *pooled;
    __half *hA, *hD, *hwh, *aggh;
    int *cnt, *cnt2, *rowptr, *gcnt, *goff;
    int2* csre;
    unsigned char* Wimg;
    cudaGetSymbolAddress((void**)&hA, g_hA);
    cudaGetSymbolAddress((void**)&hD, g_hD);
    cudaGetSymbolAddress((void**)&hwh, g_hwh);
    cudaGetSymbolAddress((void**)&aggh, g_aggh);
    cudaGetSymbolAddress((void**)&cnt, g_cnt);
    cudaGetSymbolAddress((void**)&cnt2, g_cnt2);
    cudaGetSymbolAddress((void**)&rowptr, g_rowptr);
    cudaGetSymbolAddress((void**)&csre, g_csre);
    cudaGetSymbolAddress((void**)&gcnt, g_gcnt);
    cudaGetSymbolAddress((void**)&goff, g_goff);
    cudaGetSymbolAddress((void**)&dinv, g_dinv);
    cudaGetSymbolAddress((void**)&P, g_P);
    cudaGetSymbolAddress((void**)&Q, g_Q);
    cudaGetSymbolAddress((void**)&sums, g_sums);
    cudaGetSymbolAddress((void**)&pooled, g_pooled);
    cudaGetSymbolAddress((void**)&Wimg, g_Wimg);

    cudaFuncSetAttribute(k_gemm_mma, cudaFuncAttributeMaxDynamicSharedMemorySize, SM_GEMM);

    const int TB = 256;
    const int AGG_GRID = 4096;

    cudaMemsetAsync(cnt, 0, NN * sizeof(int));
    cudaMemsetAsync(cnt2, 0, NN * sizeof(int));
    cudaMemsetAsync(gcnt, 0, GG * sizeof(int));
    cudaMemsetAsync(sums, 0, LL * 2 * HH * sizeof(float));

    // launch 0: counting + weight images + projection tables
    k_count_weights<<<3125 + 1024 + 103, TB>>>(dst, batch, cnt, gcnt,
                                               gcn_W, Wimg, atom_emb, tag_emb, Wp, bp, P, Q);
    // launch 1: scans
    k_scan<<<1, 1024>>>(cnt, rowptr, dinv, gcnt, goff);
    // launch 2: GEMM0 (embed-fused) + fused fill_csr in extra blocks
    {
        dim3 g0(2, GY_GEMM + 1563);
        k_gemm_mma<<<g0, 256, SM_GEMM>>>(nullptr, nullptr, nullptr, nullptr, nullptr,
            Wimg, hwh, NN, P, Q, x, tags, 1, hA,
            src, dst, rowptr, dinv, cnt2, csre);
    }
    // launch 3: aggregate (PROFILED)
    k_aggregate<<<AGG_GRID, 128>>>(hwh, dinv, rowptr, csre, gcn_b, aggh, sums);

    __half* hres = hA;
    __half* hnew = hD;
    dim3 ggrid(2, GY_GEMM);
    for (int l = 1; l < LL; l++) {
        k_gemm_mma<<<ggrid, 256, SM_GEMM>>>(
            aggh, hres, sums + (size_t)(l - 1) * 2 * HH,
            bn_g + (size_t)(l - 1) * HH, bn_b + (size_t)(l - 1) * HH,
            Wimg + (size_t)l * 8 * 32768, hwh, NN, P, Q, x, tags, 2, hnew,
            src, dst, rowptr, dinv, cnt2, csre);
        k_aggregate<<<AGG_GRID, 128>>>(hwh, dinv, rowptr, csre,
                                       gcn_b + (size_t)l * HH, aggh,
                                       sums + (size_t)l * 2 * HH);
        __half* tmp = hres; hres = hnew; hnew = tmp;
    }

    k_pool<<<GG, HH>>>(aggh, hres, sums + (size_t)(LL - 1) * 2 * HH,
                       bn_g + (size_t)(LL - 1) * HH, bn_b + (size_t)(LL - 1) * HH,
                       goff, pooled);
    k_mlp<<<GG, 128>>>(pooled, W1, b1, W2, b2, out);
    (void)in_sizes; (void)n_in; (void)out_size;
}